// round 2
// baseline (speedup 1.0000x reference)
#include <cuda_runtime.h>
#include <math.h>

// Problem constants (fixed by the reference)
#define NB 2
#define NT 1024
#define ND 1024
#define NV 32000
#define NL 4
#define NE 2048
#define NN 16
#define NR 64
#define NK 4
#define NXD 96          // R + 2N
#define NBT (NB*NT)     // 2048 tokens

// ---------------- scratch (static device globals; no runtime alloc) --------
static __device__ float g_x[NBT*ND];          // residual stream
static __device__ float g_xn[NBT*ND];         // layernormed
static __device__ float g_xz[(size_t)NBT*2*NE];
static __device__ float g_xc[(size_t)NBT*NE];
static __device__ float g_xdbl[NBT*NXD];
static __device__ float g_delta[(size_t)NBT*NE];
static __device__ float g_y[(size_t)NBT*NE];
static __device__ float g_nll[NBT];
static __device__ float g_logits_fb[(size_t)NBT*NV];  // fallback if d_out too small

// ---------------- helpers ---------------------------------------------------
__device__ __forceinline__ float warpSum(float v) {
#pragma unroll
    for (int o = 16; o > 0; o >>= 1) v += __shfl_xor_sync(0xffffffffu, v, o);
    return v;
}
__device__ __forceinline__ float warpMax(float v) {
#pragma unroll
    for (int o = 16; o > 0; o >>= 1) v = fmaxf(v, __shfl_xor_sync(0xffffffffu, v, o));
    return v;
}
__device__ __forceinline__ float siluf(float x) {
    return x / (1.0f + __expf(-x));
}

// ---------------- SGEMM: C[M,N] = A[M,K] * B[N,K]^T (both row-major) -------
// mode 0: store   mode 1: C += acc (residual)   mode 2: softplus(acc + bias[n])
// M must be a multiple of 128; N,K arbitrary with K%8==0.
__global__ void __launch_bounds__(256)
sgemm_kernel(const float* __restrict__ A, int lda,
             const float* __restrict__ Bw, int ldb,
             float* __restrict__ C, int ldc,
             int Nd, int Kd, int mode, const float* __restrict__ bias)
{
    __shared__ float As[8][128];
    __shared__ float Bs[8][136];   // padded so row stride is 16B multiple

    const int tid = threadIdx.x;
    const int m0 = blockIdx.y * 128;
    const int n0 = blockIdx.x * 128;
    const int tx = tid & 15;        // 0..15 (col group)
    const int ty = tid >> 4;        // 0..15 (row group)

    float acc[8][8];
#pragma unroll
    for (int i = 0; i < 8; i++)
#pragma unroll
        for (int j = 0; j < 8; j++) acc[i][j] = 0.0f;

    const int lr = tid >> 1;          // 0..127
    const int lk = (tid & 1) * 4;     // 0 or 4
    const float* Aptr = A + (size_t)(m0 + lr) * lda + lk;
    const bool bvalid = (n0 + lr) < Nd;
    const float* Bptr = Bw + (size_t)(n0 + lr) * ldb + lk;

    for (int k0 = 0; k0 < Kd; k0 += 8) {
        float4 av = *(const float4*)(Aptr + k0);
        float4 bv = bvalid ? *(const float4*)(Bptr + k0)
                           : make_float4(0.f, 0.f, 0.f, 0.f);
        __syncthreads();
        As[lk + 0][lr] = av.x; As[lk + 1][lr] = av.y;
        As[lk + 2][lr] = av.z; As[lk + 3][lr] = av.w;
        Bs[lk + 0][lr] = bv.x; Bs[lk + 1][lr] = bv.y;
        Bs[lk + 2][lr] = bv.z; Bs[lk + 3][lr] = bv.w;
        __syncthreads();

#pragma unroll
        for (int k = 0; k < 8; k++) {
            float4 a0 = *(const float4*)&As[k][ty * 8];
            float4 a1 = *(const float4*)&As[k][ty * 8 + 4];
            float4 b0 = *(const float4*)&Bs[k][tx * 8];
            float4 b1 = *(const float4*)&Bs[k][tx * 8 + 4];
            float ra[8] = {a0.x, a0.y, a0.z, a0.w, a1.x, a1.y, a1.z, a1.w};
            float rb[8] = {b0.x, b0.y, b0.z, b0.w, b1.x, b1.y, b1.z, b1.w};
#pragma unroll
            for (int i = 0; i < 8; i++)
#pragma unroll
                for (int j = 0; j < 8; j++)
                    acc[i][j] = fmaf(ra[i], rb[j], acc[i][j]);
        }
    }

#pragma unroll
    for (int i = 0; i < 8; i++) {
        const int row = m0 + ty * 8 + i;
#pragma unroll
        for (int j = 0; j < 8; j++) {
            const int col = n0 + tx * 8 + j;
            if (col < Nd) {
                float v = acc[i][j];
                size_t off = (size_t)row * ldc + col;
                if (mode == 1) {
                    v += C[off];
                } else if (mode == 2) {
                    v += bias[col];
                    v = (v > 20.0f) ? v : log1pf(__expf(v));
                }
                C[off] = v;
            }
        }
    }
}

// ---------------- embedding -------------------------------------------------
__global__ void embed_kernel(const int* __restrict__ ids,
                             const float* __restrict__ tok,
                             const float* __restrict__ pos)
{
    int idx = blockIdx.x * blockDim.x + threadIdx.x;
    if (idx >= NBT * ND) return;
    int d = idx % ND;
    int bt = idx / ND;
    int t = bt % NT;
    g_x[idx] = tok[(size_t)ids[bt] * ND + d] + pos[(size_t)t * ND + d];
}

// ---------------- causal depthwise conv (K=4) + bias + SiLU ----------------
__global__ void conv_silu_kernel(const float* __restrict__ cw,
                                 const float* __restrict__ cb)
{
    int idx = blockIdx.x * blockDim.x + threadIdx.x;
    if (idx >= NBT * NE) return;
    int e = idx % NE;
    int bt = idx / NE;
    int t = bt % NT;
    float s = cb[e];
#pragma unroll
    for (int k = 0; k < NK; k++) {
        int tt = t - (NK - 1) + k;
        if (tt >= 0)
            s += cw[e * NK + k] * g_xz[(size_t)(bt - (NK - 1) + k) * (2 * NE) + e];
    }
    g_xc[idx] = siluf(s);
}

// ---------------- selective scan + D skip + SiLU(z) gating ------------------
// One 16-lane group per (b,e) channel; lane = state index n. 256 thr = 16 ch.
__global__ void __launch_bounds__(256)
scan_kernel(const float* __restrict__ A_log,   // [E,N] slice for this layer
            const float* __restrict__ Dp)      // [E]
{
    const int tid = threadIdx.x;
    const int lane = tid & 15;
    const int ch = blockIdx.x * 16 + (tid >> 4);   // 0..B*E-1
    const int b = ch >> 11;                        // E = 2048
    const int e = ch & (NE - 1);

    const float Av = -__expf(A_log[e * NN + lane]);
    const float dpar = Dp[e];
    float h = 0.0f;
    const size_t base = (size_t)b * NT;

    for (int t = 0; t < NT; t++) {
        const size_t row = base + t;
        const float dv = g_delta[row * NE + e];
        const float xv = g_xc[row * NE + e];
        const float Bv = g_xdbl[row * NXD + NR + lane];
        const float Cv = g_xdbl[row * NXD + NR + NN + lane];
        h = __expf(dv * Av) * h + (dv * Bv) * xv;
        float p = h * Cv;
        p += __shfl_xor_sync(0xffffffffu, p, 8);
        p += __shfl_xor_sync(0xffffffffu, p, 4);
        p += __shfl_xor_sync(0xffffffffu, p, 2);
        p += __shfl_xor_sync(0xffffffffu, p, 1);
        if (lane == 0) {
            const float z = g_xz[row * (2 * NE) + NE + e];
            g_y[row * NE + e] = (p + dpar * xv) * siluf(z);
        }
    }
}

// ---------------- LayerNorm --------------------------------------------------
__global__ void ln_kernel(const float* __restrict__ gam,
                          const float* __restrict__ bet)
{
    __shared__ float sm[8], sm2[8];
    const int bt = blockIdx.x;
    const float* row = g_x + (size_t)bt * ND;
    float s = 0.f, s2 = 0.f;
    for (int d = threadIdx.x; d < ND; d += 256) {
        float v = row[d];
        s += v; s2 += v * v;
    }
    s = warpSum(s); s2 = warpSum(s2);
    if ((threadIdx.x & 31) == 0) { sm[threadIdx.x >> 5] = s; sm2[threadIdx.x >> 5] = s2; }
    __syncthreads();
    if (threadIdx.x < 32) {
        float a = threadIdx.x < 8 ? sm[threadIdx.x] : 0.f;
        float b2 = threadIdx.x < 8 ? sm2[threadIdx.x] : 0.f;
        a = warpSum(a); b2 = warpSum(b2);
        if (threadIdx.x == 0) { sm[0] = a; sm2[0] = b2; }
    }
    __syncthreads();
    const float mu = sm[0] * (1.0f / ND);
    const float var = sm2[0] * (1.0f / ND) - mu * mu;
    const float inv = rsqrtf(var + 1e-5f);
    for (int d = threadIdx.x; d < ND; d += 256)
        g_xn[(size_t)bt * ND + d] = (row[d] - mu) * inv * gam[d] + bet[d];
}

// ---------------- per-token NLL ---------------------------------------------
__global__ void loss_token_kernel(const float* __restrict__ logits,
                                  const int* __restrict__ tgt)
{
    __shared__ float sred[8];
    const int bt = blockIdx.x;
    const float* row = logits + (size_t)bt * NV;

    float m = -1e30f;
    for (int v = threadIdx.x; v < NV; v += 256) m = fmaxf(m, row[v]);
    m = warpMax(m);
    if ((threadIdx.x & 31) == 0) sred[threadIdx.x >> 5] = m;
    __syncthreads();
    if (threadIdx.x < 32) {
        float a = threadIdx.x < 8 ? sred[threadIdx.x] : -1e30f;
        a = warpMax(a);
        if (threadIdx.x == 0) sred[0] = a;
    }
    __syncthreads();
    m = sred[0];
    __syncthreads();

    float se = 0.f;
    for (int v = threadIdx.x; v < NV; v += 256) se += __expf(row[v] - m);
    se = warpSum(se);
    if ((threadIdx.x & 31) == 0) sred[threadIdx.x >> 5] = se;
    __syncthreads();
    if (threadIdx.x < 32) {
        float a = threadIdx.x < 8 ? sred[threadIdx.x] : 0.f;
        a = warpSum(a);
        if (threadIdx.x == 0) {
            int tv = tgt[bt];
            float val = 0.0f;
            if (tv != -100) val = -(row[tv] - m - logf(a));
            g_nll[bt] = val;
        }
    }
}

__global__ void loss_reduce_kernel(const int* __restrict__ tgt,
                                   float* __restrict__ out)
{
    __shared__ float sm[32], sc[32];
    float s = 0.f, c = 0.f;
    for (int i = threadIdx.x; i < NBT; i += 1024) {
        s += g_nll[i];
        c += (tgt[i] != -100) ? 1.0f : 0.0f;
    }
    s = warpSum(s); c = warpSum(c);
    if ((threadIdx.x & 31) == 0) { sm[threadIdx.x >> 5] = s; sc[threadIdx.x >> 5] = c; }
    __syncthreads();
    if (threadIdx.x < 32) {
        float a = sm[threadIdx.x];
        float b = sc[threadIdx.x];
        a = warpSum(a); b = warpSum(b);
        if (threadIdx.x == 0) out[0] = a / fmaxf(b, 1.0f);
    }
}

// ---------------- host orchestration ----------------------------------------
extern "C" void kernel_launch(void* const* d_in, const int* in_sizes, int n_in,
                              void* d_out, int out_size)
{
    const int*   ids        = (const int*)d_in[0];
    const int*   tgt        = (const int*)d_in[1];
    const float* tok_emb    = (const float*)d_in[2];
    const float* pos_emb    = (const float*)d_in[3];
    const float* ln_g       = (const float*)d_in[4];
    const float* ln_b       = (const float*)d_in[5];
    const float* head_w     = (const float*)d_in[6];
    const float* in_proj_w  = (const float*)d_in[7];
    const float* conv_w     = (const float*)d_in[8];
    const float* conv_b     = (const float*)d_in[9];
    const float* x_proj_w   = (const float*)d_in[10];
    const float* dt_proj_w  = (const float*)d_in[11];
    const float* dt_proj_b  = (const float*)d_in[12];
    const float* A_log      = (const float*)d_in[13];
    const float* D_param    = (const float*)d_in[14];
    const float* out_proj_w = (const float*)d_in[15];
    float* out = (float*)d_out;

    // Resolve scratch addresses (lookup only — no allocation).
    float *px, *pxn, *pxz, *pxc, *pxdbl, *pdelta, *py, *plogits_fb;
    cudaGetSymbolAddress((void**)&px,        g_x);
    cudaGetSymbolAddress((void**)&pxn,       g_xn);
    cudaGetSymbolAddress((void**)&pxz,       g_xz);
    cudaGetSymbolAddress((void**)&pxc,       g_xc);
    cudaGetSymbolAddress((void**)&pxdbl,     g_xdbl);
    cudaGetSymbolAddress((void**)&pdelta,    g_delta);
    cudaGetSymbolAddress((void**)&py,        g_y);
    cudaGetSymbolAddress((void**)&plogits_fb,g_logits_fb);

    const long long NLOGITS = (long long)NBT * NV;

    // 1) embedding
    embed_kernel<<<(NBT * ND + 255) / 256, 256>>>(ids, tok_emb, pos_emb);

    // 2) layers
    for (int l = 0; l < NL; l++) {
        // xz = x @ in_proj_w[l]^T   [2048 x 4096]
        sgemm_kernel<<<dim3(4096 / 128, NBT / 128), 256>>>(
            px, ND, in_proj_w + (size_t)l * 2 * NE * ND, ND,
            pxz, 2 * NE, 2 * NE, ND, 0, nullptr);

        // causal conv + SiLU -> xc
        conv_silu_kernel<<<(NBT * NE + 255) / 256, 256>>>(
            conv_w + (size_t)l * NE * NK, conv_b + (size_t)l * NE);

        // x_dbl = xc @ x_proj_w[l]^T   [2048 x 96]
        sgemm_kernel<<<dim3(1, NBT / 128), 256>>>(
            pxc, NE, x_proj_w + (size_t)l * NXD * NE, NE,
            pxdbl, NXD, NXD, NE, 0, nullptr);

        // delta = softplus(dt @ dt_proj_w[l]^T + dt_proj_b[l])  [2048 x 2048]
        sgemm_kernel<<<dim3(NE / 128, NBT / 128), 256>>>(
            pxdbl, NXD, dt_proj_w + (size_t)l * NE * NR, NR,
            pdelta, NE, NE, NR, 2, dt_proj_b + (size_t)l * NE);

        // selective scan + gating -> y
        scan_kernel<<<(NB * NE) / 16, 256>>>(
            A_log + (size_t)l * NE * NN, D_param + (size_t)l * NE);

        // x += y @ out_proj_w[l]^T    [2048 x 1024]
        sgemm_kernel<<<dim3(ND / 128, NBT / 128), 256>>>(
            py, NE, out_proj_w + (size_t)l * ND * NE, NE,
            px, ND, ND, NE, 1, nullptr);
    }

    // 3) final LayerNorm
    ln_kernel<<<NBT, 256>>>(ln_g, ln_b);

    // 4) head GEMM -> logits (into d_out if it fits, else fallback scratch)
    float* logits = ((long long)out_size >= NLOGITS) ? out : plogits_fb;
    sgemm_kernel<<<dim3((NV + 127) / 128, NBT / 128), 256>>>(
        pxn, ND, head_w, ND, logits, NV, NV, ND, 0, nullptr);

    // 5) loss
    loss_token_kernel<<<NBT, 256>>>(logits, tgt);
    float* lossptr = nullptr;
    if ((long long)out_size > NLOGITS)      lossptr = out + NLOGITS;  // [logits..., loss]
    else if ((long long)out_size < NLOGITS) lossptr = out;            // loss-only output
    if (lossptr)
        loss_reduce_kernel<<<1, 1024>>>(tgt, lossptr);
}

// round 5
// speedup vs baseline: 1.6417x; 1.6417x over previous
#include <cuda_runtime.h>
#include <cuda_bf16.h>
#include <math.h>
#include <stdint.h>

// Problem constants (fixed by the reference)
#define NB 2
#define NT 1024
#define ND 1024
#define NV 32000
#define NL 4
#define NE 2048
#define NN 16
#define NR 64
#define NKC 4
#define NXD 96
#define NBT (NB*NT)

// ---------------- single scratch region (one device symbol) -----------------
constexpr size_t OFF_X     = 0;
constexpr size_t OFF_XZ    = OFF_X     + (size_t)NBT*ND*4;
constexpr size_t OFF_XC    = OFF_XZ    + (size_t)NBT*2*NE*4;
constexpr size_t OFF_DELTA = OFF_XC    + (size_t)NBT*NE*4;
constexpr size_t OFF_XDBL  = OFF_DELTA + (size_t)NBT*NE*4;
constexpr size_t OFF_NLL   = OFF_XDBL  + (size_t)NBT*128*4;
constexpr size_t OFF_XHI   = OFF_NLL   + (size_t)1024*1024;
constexpr size_t OFF_XLO   = OFF_XHI   + (size_t)NBT*ND*2;
constexpr size_t OFF_XCHI  = OFF_XLO   + (size_t)NBT*ND*2;
constexpr size_t OFF_XCLO  = OFF_XCHI  + (size_t)NBT*NE*2;
constexpr size_t OFF_YHI   = OFF_XCLO  + (size_t)NBT*NE*2;
constexpr size_t OFF_YLO   = OFF_YHI   + (size_t)NBT*NE*2;
constexpr size_t OFF_XNHI  = OFF_YLO   + (size_t)NBT*NE*2;
constexpr size_t OFF_XNLO  = OFF_XNHI  + (size_t)NBT*ND*2;
constexpr size_t OFF_WIH   = OFF_XNLO  + (size_t)NBT*ND*2;
constexpr size_t OFF_WIL   = OFF_WIH   + (size_t)NL*2*NE*ND*2;
constexpr size_t OFF_WOH   = OFF_WIL   + (size_t)NL*2*NE*ND*2;
constexpr size_t OFF_WOL   = OFF_WOH   + (size_t)NL*ND*NE*2;
constexpr size_t OFF_WPH   = OFF_WOL   + (size_t)NL*ND*NE*2;
constexpr size_t OFF_WPL   = OFF_WPH   + (size_t)NL*128*NE*2;
constexpr size_t OFF_WHH   = OFF_WPL   + (size_t)NL*128*NE*2;
constexpr size_t OFF_WHL   = OFF_WHH   + (size_t)NV*ND*2;
constexpr size_t OFF_LOGFB = OFF_WHL   + (size_t)NV*ND*2;
constexpr size_t SCRATCH_SZ = OFF_LOGFB + (size_t)NBT*NV*4;

static __device__ __align__(1024) unsigned char g_scratch[SCRATCH_SZ];

__device__ __forceinline__ float* scr_f(size_t off) {
    return reinterpret_cast<float*>(g_scratch + off);
}
__device__ __forceinline__ __nv_bfloat16* scr_h(size_t off) {
    return reinterpret_cast<__nv_bfloat16*>(g_scratch + off);
}

// ---------------- helpers ----------------------------------------------------
__device__ __forceinline__ float warpSum(float v) {
#pragma unroll
    for (int o = 16; o > 0; o >>= 1) v += __shfl_xor_sync(0xffffffffu, v, o);
    return v;
}
__device__ __forceinline__ float warpMax(float v) {
#pragma unroll
    for (int o = 16; o > 0; o >>= 1) v = fmaxf(v, __shfl_xor_sync(0xffffffffu, v, o));
    return v;
}
__device__ __forceinline__ float siluf(float x) { return x / (1.0f + __expf(-x)); }

__device__ __forceinline__ void split_bf16(float x, __nv_bfloat16& hi, __nv_bfloat16& lo) {
    hi = __float2bfloat16_rn(x);
    lo = __float2bfloat16_rn(x - __bfloat162float(hi));
}

__device__ __forceinline__ uint32_t smem_u32(const void* p) {
    uint32_t a;
    asm("{ .reg .u64 t; cvta.to.shared.u64 t, %1; cvt.u32.u64 %0, t; }" : "=r"(a) : "l"(p));
    return a;
}
__device__ __forceinline__ uint32_t lds32(uint32_t a) {
    uint32_t v;
    asm volatile("ld.shared.b32 %0, [%1];" : "=r"(v) : "r"(a));
    return v;
}
__device__ __forceinline__ void cpasync16(uint32_t dst, const void* src) {
    asm volatile("cp.async.cg.shared.global [%0], [%1], 16;" :: "r"(dst), "l"(src));
}
__device__ __forceinline__ void cp_commit() {
    asm volatile("cp.async.commit_group;" ::: "memory");
}
template <int N>
__device__ __forceinline__ void cp_wait() {
    asm volatile("cp.async.wait_group %0;" :: "n"(N) : "memory");
}
__device__ __forceinline__ void mma16816(float* c, const uint32_t* a, const uint32_t* b) {
    asm volatile(
        "mma.sync.aligned.m16n8k16.row.col.f32.bf16.bf16.f32 "
        "{%0,%1,%2,%3},{%4,%5,%6,%7},{%8,%9},{%0,%1,%2,%3};"
        : "+f"(c[0]), "+f"(c[1]), "+f"(c[2]), "+f"(c[3])
        : "r"(a[0]), "r"(a[1]), "r"(a[2]), "r"(a[3]), "r"(b[0]), "r"(b[1]));
}

// ---------------- tensor-core GEMM (bf16x3 split, mma.sync) ------------------
// C[M,N] = A[M,K]*B[N,K]^T. A/B as bf16 hi/lo pairs, row-major, K%32==0.
// 128x128 CTA tile, 256 threads (8 warps, 2x4), K-chunks of 32, cp.async
// double-buffered. mode 0: store; mode 1: C += acc. auxhi/auxlo: bf16 split out.
#define TROW 40                 // smem row stride in bf16 elems (80B, conflict-free)
#define TILEB (128*TROW*2)      // 10240 bytes per tile
#define GSMEM (2*4*TILEB)       // 81920 bytes

__global__ void __launch_bounds__(256, 1)
gemm_mma(const __nv_bfloat16* __restrict__ Ahi, const __nv_bfloat16* __restrict__ Alo,
         const __nv_bfloat16* __restrict__ Bhi, const __nv_bfloat16* __restrict__ Blo,
         float* __restrict__ C, int K, int ldc, int Nreal, int mode,
         __nv_bfloat16* __restrict__ auxhi, __nv_bfloat16* __restrict__ auxlo)
{
    extern __shared__ char dynsmem[];
    const uint32_t sb = smem_u32(dynsmem);
    const int tid = threadIdx.x;
    const int wid = tid >> 5;
    const int lane = tid & 31;
    const int wm = wid >> 2;          // 0..1  (64-row slab)
    const int wn = wid & 3;           // 0..3  (32-col slab)
    const int g = lane >> 2;          // 0..7
    const int t2 = (lane & 3) * 2;

    const int m0 = blockIdx.y * 128;
    const int n0 = blockIdx.x * 128;

    const __nv_bfloat16* srcs[4];
    srcs[0] = Ahi + (size_t)m0 * K;
    srcs[1] = Alo + (size_t)m0 * K;
    srcs[2] = Bhi + (size_t)n0 * K;
    srcs[3] = Blo + (size_t)n0 * K;

    float acc[4][4][4];
#pragma unroll
    for (int mi = 0; mi < 4; mi++)
#pragma unroll
        for (int ni = 0; ni < 4; ni++)
#pragma unroll
            for (int q = 0; q < 4; q++) acc[mi][ni][q] = 0.0f;

    const int nchunks = K >> 5;

    // issue chunk 0 into buf 0
    {
        const uint32_t tb0 = sb;
#pragma unroll
        for (int t = 0; t < 4; t++) {
            const __nv_bfloat16* s = srcs[t];
#pragma unroll
            for (int u = 0; u < 2; u++) {
                const int idx = tid + u * 256;       // 0..511
                const int row = idx >> 2;
                const int seg = idx & 3;
                cpasync16(tb0 + (uint32_t)t * TILEB + (uint32_t)(row * 80 + seg * 16),
                          s + (size_t)row * K + seg * 8);
            }
        }
        cp_commit();
    }

    for (int c = 0; c < nchunks; c++) {
        const int buf = c & 1;
        if (c + 1 < nchunks) {
            const uint32_t tb1 = sb + (uint32_t)(buf ^ 1) * (4 * TILEB);
            const int k1 = (c + 1) << 5;
#pragma unroll
            for (int t = 0; t < 4; t++) {
                const __nv_bfloat16* s = srcs[t] + k1;
#pragma unroll
                for (int u = 0; u < 2; u++) {
                    const int idx = tid + u * 256;
                    const int row = idx >> 2;
                    const int seg = idx & 3;
                    cpasync16(tb1 + (uint32_t)t * TILEB + (uint32_t)(row * 80 + seg * 16),
                              s + (size_t)row * K + seg * 8);
                }
            }
            cp_commit();
            cp_wait<1>();
        } else {
            cp_wait<0>();
        }
        __syncthreads();

        const uint32_t aAh = sb + (uint32_t)buf * (4 * TILEB);
        const uint32_t aAl = aAh + TILEB;
        const uint32_t aBh = aAh + 2 * TILEB;
        const uint32_t aBl = aAh + 3 * TILEB;

#pragma unroll
        for (int ks = 0; ks < 32; ks += 16) {
            uint32_t ah[4][4], al[4][4];
#pragma unroll
            for (int mi = 0; mi < 4; mi++) {
                const int r0 = wm * 64 + mi * 16 + g;
                const uint32_t o00 = (uint32_t)(r0 * 80 + (ks + t2) * 2);
                const uint32_t o10 = o00 + 8 * 80;
                ah[mi][0] = lds32(aAh + o00);
                ah[mi][1] = lds32(aAh + o10);
                ah[mi][2] = lds32(aAh + o00 + 16);
                ah[mi][3] = lds32(aAh + o10 + 16);
                al[mi][0] = lds32(aAl + o00);
                al[mi][1] = lds32(aAl + o10);
                al[mi][2] = lds32(aAl + o00 + 16);
                al[mi][3] = lds32(aAl + o10 + 16);
            }
            uint32_t bh[4][2], bl[4][2];
#pragma unroll
            for (int ni = 0; ni < 4; ni++) {
                const int rb = wn * 32 + ni * 8 + g;
                const uint32_t ob = (uint32_t)(rb * 80 + (ks + t2) * 2);
                bh[ni][0] = lds32(aBh + ob);
                bh[ni][1] = lds32(aBh + ob + 16);
                bl[ni][0] = lds32(aBl + ob);
                bl[ni][1] = lds32(aBl + ob + 16);
            }
#pragma unroll
            for (int mi = 0; mi < 4; mi++) {
#pragma unroll
                for (int ni = 0; ni < 4; ni++) {
                    mma16816(acc[mi][ni], ah[mi], bh[ni]);
                    mma16816(acc[mi][ni], ah[mi], bl[ni]);
                    mma16816(acc[mi][ni], al[mi], bh[ni]);
                }
            }
        }
        __syncthreads();
    }

    // epilogue
#pragma unroll
    for (int mi = 0; mi < 4; mi++) {
        const int row0 = m0 + wm * 64 + mi * 16 + g;
        const int row1 = row0 + 8;
#pragma unroll
        for (int ni = 0; ni < 4; ni++) {
            const int col = n0 + wn * 32 + ni * 8 + t2;
            if (col < Nreal) {
                float v0 = acc[mi][ni][0];
                float v1 = acc[mi][ni][1];
                float v2 = acc[mi][ni][2];
                float v3 = acc[mi][ni][3];
                float* p0 = C + (size_t)row0 * ldc + col;
                float* p1 = C + (size_t)row1 * ldc + col;
                if (mode == 1) {
                    v0 += p0[0]; v1 += p0[1];
                    v2 += p1[0]; v3 += p1[1];
                }
                p0[0] = v0; p0[1] = v1;
                p1[0] = v2; p1[1] = v3;
                if (auxhi != nullptr) {
                    __nv_bfloat16 h, l;
                    split_bf16(v0, h, l);
                    auxhi[(size_t)row0 * ldc + col] = h;
                    auxlo[(size_t)row0 * ldc + col] = l;
                    split_bf16(v1, h, l);
                    auxhi[(size_t)row0 * ldc + col + 1] = h;
                    auxlo[(size_t)row0 * ldc + col + 1] = l;
                    split_bf16(v2, h, l);
                    auxhi[(size_t)row1 * ldc + col] = h;
                    auxlo[(size_t)row1 * ldc + col] = l;
                    split_bf16(v3, h, l);
                    auxhi[(size_t)row1 * ldc + col + 1] = h;
                    auxlo[(size_t)row1 * ldc + col + 1] = l;
                }
            }
        }
    }
}

// ---------------- weight conversions -----------------------------------------
__global__ void cvt_kernel(const float* __restrict__ src,
                           __nv_bfloat16* __restrict__ hi,
                           __nv_bfloat16* __restrict__ lo, long long n)
{
    long long i = (long long)blockIdx.x * blockDim.x + threadIdx.x;
    if (i >= n) return;
    __nv_bfloat16 h, l;
    split_bf16(src[i], h, l);
    hi[i] = h;
    lo[i] = l;
}

__global__ void cvt_xp_kernel(const float* __restrict__ src)
{
    int i = blockIdx.x * blockDim.x + threadIdx.x;
    if (i >= NL * 128 * NE) return;
    int col = i % NE;
    int r = (i / NE) & 127;
    int l = i / (NE * 128);
    float v = 0.0f;
    if (r < NXD) v = src[((size_t)l * NXD + r) * NE + col];
    __nv_bfloat16 h, lo2;
    split_bf16(v, h, lo2);
    scr_h(OFF_WPH)[i] = h;
    scr_h(OFF_WPL)[i] = lo2;
}

// ---------------- fp32 SGEMM (dt_proj only; softplus epilogue) ---------------
__global__ void __launch_bounds__(256)
sgemm_kernel(const float* __restrict__ A, int lda,
             const float* __restrict__ Bw, int ldb,
             float* __restrict__ C, int ldc,
             int Nd, int Kd, const float* __restrict__ bias)
{
    __shared__ float As[8][128];
    __shared__ float Bs[8][136];

    const int tid = threadIdx.x;
    const int m0 = blockIdx.y * 128;
    const int n0 = blockIdx.x * 128;
    const int tx = tid & 15;
    const int ty = tid >> 4;

    float acc[8][8];
#pragma unroll
    for (int i = 0; i < 8; i++) {
#pragma unroll
        for (int j = 0; j < 8; j++) acc[i][j] = 0.0f;
    }

    const int lr = tid >> 1;
    const int lk = (tid & 1) * 4;
    const float* Aptr = A + (size_t)(m0 + lr) * lda + lk;
    const bool bvalid = (n0 + lr) < Nd;
    const float* Bptr = Bw + (size_t)(n0 + lr) * ldb + lk;

    for (int k0 = 0; k0 < Kd; k0 += 8) {
        float4 av = *reinterpret_cast<const float4*>(Aptr + k0);
        float4 bv = make_float4(0.f, 0.f, 0.f, 0.f);
        if (bvalid) bv = *reinterpret_cast<const float4*>(Bptr + k0);
        __syncthreads();
        As[lk + 0][lr] = av.x; As[lk + 1][lr] = av.y;
        As[lk + 2][lr] = av.z; As[lk + 3][lr] = av.w;
        Bs[lk + 0][lr] = bv.x; Bs[lk + 1][lr] = bv.y;
        Bs[lk + 2][lr] = bv.z; Bs[lk + 3][lr] = bv.w;
        __syncthreads();

#pragma unroll
        for (int k = 0; k < 8; k++) {
            float ra[8], rb[8];
#pragma unroll
            for (int j = 0; j < 8; j++) ra[j] = As[k][ty * 8 + j];
#pragma unroll
            for (int j = 0; j < 8; j++) rb[j] = Bs[k][tx * 8 + j];
#pragma unroll
            for (int i = 0; i < 8; i++) {
#pragma unroll
                for (int j = 0; j < 8; j++) acc[i][j] = fmaf(ra[i], rb[j], acc[i][j]);
            }
        }
    }

#pragma unroll
    for (int i = 0; i < 8; i++) {
        const int row = m0 + ty * 8 + i;
#pragma unroll
        for (int j = 0; j < 8; j++) {
            const int col = n0 + tx * 8 + j;
            if (col < Nd) {
                float v = acc[i][j] + bias[col];
                v = (v > 20.0f) ? v : log1pf(__expf(v));
                C[(size_t)row * ldc + col] = v;
            }
        }
    }
}

// ---------------- embedding ---------------------------------------------------
__global__ void embed_kernel(const int* __restrict__ ids,
                             const float* __restrict__ tok,
                             const float* __restrict__ pos)
{
    int idx = blockIdx.x * blockDim.x + threadIdx.x;
    if (idx >= NBT * ND) return;
    int d = idx % ND;
    int bt = idx / ND;
    int t = bt % NT;
    float v = tok[(size_t)ids[bt] * ND + d] + pos[(size_t)t * ND + d];
    scr_f(OFF_X)[idx] = v;
    __nv_bfloat16 h, l;
    split_bf16(v, h, l);
    scr_h(OFF_XHI)[idx] = h;
    scr_h(OFF_XLO)[idx] = l;
}

// ---------------- causal depthwise conv + bias + SiLU ------------------------
__global__ void conv_silu_kernel(const float* __restrict__ cw,
                                 const float* __restrict__ cb)
{
    int idx = blockIdx.x * blockDim.x + threadIdx.x;
    if (idx >= NBT * NE) return;
    const float* xz = scr_f(OFF_XZ);
    int e = idx % NE;
    int bt = idx / NE;
    int t = bt % NT;
    float s = cb[e];
#pragma unroll
    for (int k = 0; k < NKC; k++) {
        int tt = t - (NKC - 1) + k;
        if (tt >= 0)
            s += cw[e * NKC + k] * xz[(size_t)(bt - (NKC - 1) + k) * (2 * NE) + e];
    }
    float v = siluf(s);
    scr_f(OFF_XC)[idx] = v;
    __nv_bfloat16 h, l;
    split_bf16(v, h, l);
    scr_h(OFF_XCHI)[idx] = h;
    scr_h(OFF_XCLO)[idx] = l;
}

// ---------------- selective scan + D skip + SiLU(z) gate ---------------------
__global__ void __launch_bounds__(256)
scan_kernel(const float* __restrict__ A_log, const float* __restrict__ Dp)
{
    const int tid = threadIdx.x;
    const int lane = tid & 15;
    const int ch = blockIdx.x * 16 + (tid >> 4);
    const int b = ch >> 11;
    const int e = ch & (NE - 1);

    const float* delta = scr_f(OFF_DELTA);
    const float* xc = scr_f(OFF_XC);
    const float* xdbl = scr_f(OFF_XDBL);
    const float* xz = scr_f(OFF_XZ);
    __nv_bfloat16* yhi = scr_h(OFF_YHI);
    __nv_bfloat16* ylo = scr_h(OFF_YLO);

    const float Av = -__expf(A_log[e * NN + lane]);
    const float dpar = Dp[e];
    float h = 0.0f;
    const size_t base = (size_t)b * NT;

    for (int t = 0; t < NT; t++) {
        const size_t row = base + t;
        const float dv = delta[row * NE + e];
        const float xv = xc[row * NE + e];
        const float Bv = xdbl[row * NXD + NR + lane];
        const float Cv = xdbl[row * NXD + NR + NN + lane];
        h = __expf(dv * Av) * h + (dv * Bv) * xv;
        float p = h * Cv;
        p += __shfl_xor_sync(0xffffffffu, p, 8);
        p += __shfl_xor_sync(0xffffffffu, p, 4);
        p += __shfl_xor_sync(0xffffffffu, p, 2);
        p += __shfl_xor_sync(0xffffffffu, p, 1);
        if (lane == 0) {
            const float z = xz[row * (2 * NE) + NE + e];
            float v = (p + dpar * xv) * siluf(z);
            __nv_bfloat16 hh, ll;
            split_bf16(v, hh, ll);
            yhi[row * NE + e] = hh;
            ylo[row * NE + e] = ll;
        }
    }
}

// ---------------- LayerNorm ---------------------------------------------------
__global__ void ln_kernel(const float* __restrict__ gam,
                          const float* __restrict__ bet)
{
    __shared__ float sm[8];
    __shared__ float sm2[8];
    const int bt = blockIdx.x;
    const float* row = scr_f(OFF_X) + (size_t)bt * ND;
    float s = 0.f, s2 = 0.f;
    for (int d = threadIdx.x; d < ND; d += 256) {
        float v = row[d];
        s += v;
        s2 += v * v;
    }
    s = warpSum(s);
    s2 = warpSum(s2);
    if ((threadIdx.x & 31) == 0) { sm[threadIdx.x >> 5] = s; sm2[threadIdx.x >> 5] = s2; }
    __syncthreads();
    if (threadIdx.x < 32) {
        float a = (threadIdx.x < 8) ? sm[threadIdx.x] : 0.f;
        float b2 = (threadIdx.x < 8) ? sm2[threadIdx.x] : 0.f;
        a = warpSum(a);
        b2 = warpSum(b2);
        if (threadIdx.x == 0) { sm[0] = a; sm2[0] = b2; }
    }
    __syncthreads();
    const float mu = sm[0] * (1.0f / ND);
    const float var = sm2[0] * (1.0f / ND) - mu * mu;
    const float inv = rsqrtf(var + 1e-5f);
    for (int d = threadIdx.x; d < ND; d += 256) {
        float v = (row[d] - mu) * inv * gam[d] + bet[d];
        __nv_bfloat16 h, l;
        split_bf16(v, h, l);
        scr_h(OFF_XNHI)[(size_t)bt * ND + d] = h;
        scr_h(OFF_XNLO)[(size_t)bt * ND + d] = l;
    }
}

// ---------------- per-token NLL ----------------------------------------------
__global__ void loss_token_kernel(const float* __restrict__ logits,
                                  const int* __restrict__ tgt)
{
    __shared__ float sred[8];
    const int bt = blockIdx.x;
    const float* row = logits + (size_t)bt * NV;

    float m = -1e30f;
    for (int v = threadIdx.x; v < NV; v += 256) m = fmaxf(m, row[v]);
    m = warpMax(m);
    if ((threadIdx.x & 31) == 0) sred[threadIdx.x >> 5] = m;
    __syncthreads();
    if (threadIdx.x < 32) {
        float a = (threadIdx.x < 8) ? sred[threadIdx.x] : -1e30f;
        a = warpMax(a);
        if (threadIdx.x == 0) sred[0] = a;
    }
    __syncthreads();
    m = sred[0];
    __syncthreads();

    float se = 0.f;
    for (int v = threadIdx.x; v < NV; v += 256) se += __expf(row[v] - m);
    se = warpSum(se);
    if ((threadIdx.x & 31) == 0) sred[threadIdx.x >> 5] = se;
    __syncthreads();
    if (threadIdx.x < 32) {
        float a = (threadIdx.x < 8) ? sred[threadIdx.x] : 0.f;
        a = warpSum(a);
        if (threadIdx.x == 0) {
            int tv = tgt[bt];
            float val = 0.0f;
            if (tv != -100) val = -(row[tv] - m - logf(a));
            scr_f(OFF_NLL)[bt] = val;
        }
    }
}

__global__ void loss_reduce_kernel(const int* __restrict__ tgt,
                                   float* __restrict__ outp)
{
    __shared__ float sm[32];
    __shared__ float sc[32];
    float s = 0.f, c = 0.f;
    for (int i = threadIdx.x; i < NBT; i += 1024) {
        s += scr_f(OFF_NLL)[i];
        c += (tgt[i] != -100) ? 1.0f : 0.0f;
    }
    s = warpSum(s);
    c = warpSum(c);
    if ((threadIdx.x & 31) == 0) { sm[threadIdx.x >> 5] = s; sc[threadIdx.x >> 5] = c; }
    __syncthreads();
    if (threadIdx.x < 32) {
        float a = sm[threadIdx.x];
        float b = sc[threadIdx.x];
        a = warpSum(a);
        b = warpSum(b);
        if (threadIdx.x == 0) outp[0] = a / fmaxf(b, 1.0f);
    }
}

// ---------------- host orchestration -----------------------------------------
extern "C" void kernel_launch(void* const* d_in, const int* in_sizes, int n_in,
                              void* d_out, int out_size)
{
    const int* ids = (const int*)d_in[0];
    const int* tgt = (const int*)d_in[1];
    const float* tok_emb = (const float*)d_in[2];
    const float* pos_emb = (const float*)d_in[3];
    const float* ln_g = (const float*)d_in[4];
    const float* ln_b = (const float*)d_in[5];
    const float* head_w = (const float*)d_in[6];
    const float* in_proj_w = (const float*)d_in[7];
    const float* conv_w = (const float*)d_in[8];
    const float* conv_b = (const float*)d_in[9];
    const float* x_proj_w = (const float*)d_in[10];
    const float* dt_proj_w = (const float*)d_in[11];
    const float* dt_proj_b = (const float*)d_in[12];
    const float* A_log = (const float*)d_in[13];
    const float* D_param = (const float*)d_in[14];
    const float* out_proj_w = (const float*)d_in[15];
    float* out = (float*)d_out;

    unsigned char* base = 0;
    cudaGetSymbolAddress((void**)&base, g_scratch);

    float* p_x = (float*)(base + OFF_X);
    float* p_xz = (float*)(base + OFF_XZ);
    float* p_xdbl = (float*)(base + OFF_XDBL);
    float* p_delta = (float*)(base + OFF_DELTA);
    float* p_logfb = (float*)(base + OFF_LOGFB);
    __nv_bfloat16* p_xhi = (__nv_bfloat16*)(base + OFF_XHI);
    __nv_bfloat16* p_xlo = (__nv_bfloat16*)(base + OFF_XLO);
    __nv_bfloat16* p_xchi = (__nv_bfloat16*)(base + OFF_XCHI);
    __nv_bfloat16* p_xclo = (__nv_bfloat16*)(base + OFF_XCLO);
    __nv_bfloat16* p_yhi = (__nv_bfloat16*)(base + OFF_YHI);
    __nv_bfloat16* p_ylo = (__nv_bfloat16*)(base + OFF_YLO);
    __nv_bfloat16* p_xnhi = (__nv_bfloat16*)(base + OFF_XNHI);
    __nv_bfloat16* p_xnlo = (__nv_bfloat16*)(base + OFF_XNLO);
    __nv_bfloat16* p_wih = (__nv_bfloat16*)(base + OFF_WIH);
    __nv_bfloat16* p_wil = (__nv_bfloat16*)(base + OFF_WIL);
    __nv_bfloat16* p_woh = (__nv_bfloat16*)(base + OFF_WOH);
    __nv_bfloat16* p_wol = (__nv_bfloat16*)(base + OFF_WOL);
    __nv_bfloat16* p_wph = (__nv_bfloat16*)(base + OFF_WPH);
    __nv_bfloat16* p_wpl = (__nv_bfloat16*)(base + OFF_WPL);
    __nv_bfloat16* p_whh = (__nv_bfloat16*)(base + OFF_WHH);
    __nv_bfloat16* p_whl = (__nv_bfloat16*)(base + OFF_WHL);

    cudaFuncSetAttribute(gemm_mma, cudaFuncAttributeMaxDynamicSharedMemorySize, GSMEM);

    const long long NLOGITS = (long long)NBT * NV;

    // 0) weight conversions (rebuilt every launch; deterministic)
    {
        long long n1 = (long long)NL * 2 * NE * ND;
        cvt_kernel<<<(int)((n1 + 255) / 256), 256>>>(in_proj_w, p_wih, p_wil, n1);
        long long n2 = (long long)NL * ND * NE;
        cvt_kernel<<<(int)((n2 + 255) / 256), 256>>>(out_proj_w, p_woh, p_wol, n2);
        long long n3 = (long long)NV * ND;
        cvt_kernel<<<(int)((n3 + 255) / 256), 256>>>(head_w, p_whh, p_whl, n3);
        cvt_xp_kernel<<<(NL * 128 * NE + 255) / 256, 256>>>(x_proj_w);
    }

    // 1) embedding
    embed_kernel<<<(NBT * ND + 255) / 256, 256>>>(ids, tok_emb, pos_emb);

    // 2) layers
    for (int l = 0; l < NL; l++) {
        // xz = x @ in_proj^T   [2048 x 4096], K=1024
        gemm_mma<<<dim3(32, 16), 256, GSMEM>>>(
            p_xhi, p_xlo,
            p_wih + (size_t)l * 2 * NE * ND, p_wil + (size_t)l * 2 * NE * ND,
            p_xz, ND, 2 * NE, 2 * NE, 0, nullptr, nullptr);

        // conv + SiLU -> xc
        conv_silu_kernel<<<(NBT * NE + 255) / 256, 256>>>(
            conv_w + (size_t)l * NE * NKC, conv_b + (size_t)l * NE);

        // x_dbl = xc @ x_proj^T   [2048 x 96] (N padded to 128), K=2048
        gemm_mma<<<dim3(1, 16), 256, GSMEM>>>(
            p_xchi, p_xclo,
            p_wph + (size_t)l * 128 * NE, p_wpl + (size_t)l * 128 * NE,
            p_xdbl, NE, NXD, NXD, 0, nullptr, nullptr);

        // delta = softplus(dt @ dt_proj^T + b)   [2048 x 2048], K=64
        sgemm_kernel<<<dim3(16, 16), 256>>>(
            p_xdbl, NXD, dt_proj_w + (size_t)l * NE * NR, NR,
            p_delta, NE, NE, NR, dt_proj_b + (size_t)l * NE);

        // selective scan -> y (bf16 split)
        scan_kernel<<<(NB * NE) / 16, 256>>>(
            A_log + (size_t)l * NE * NN, D_param + (size_t)l * NE);

        // x += y @ out_proj^T   [2048 x 1024], K=2048; fused x hi/lo refresh
        gemm_mma<<<dim3(8, 16), 256, GSMEM>>>(
            p_yhi, p_ylo,
            p_woh + (size_t)l * ND * NE, p_wol + (size_t)l * ND * NE,
            p_x, NE, ND, ND, 1, p_xhi, p_xlo);
    }

    // 3) final LayerNorm
    ln_kernel<<<NBT, 256>>>(ln_g, ln_b);

    // 4) head GEMM -> logits  [2048 x 32000], K=1024
    float* logits = ((long long)out_size >= NLOGITS) ? out : p_logfb;
    gemm_mma<<<dim3(250, 16), 256, GSMEM>>>(
        p_xnhi, p_xnlo, p_whh, p_whl,
        logits, ND, NV, NV, 0, nullptr, nullptr);

    // 5) loss
    loss_token_kernel<<<NBT, 256>>>(logits, tgt);
    float* lossptr = nullptr;
    if ((long long)out_size > NLOGITS) lossptr = out + NLOGITS;
    else if ((long long)out_size < NLOGITS) lossptr = out;
    if (lossptr != nullptr)
        loss_reduce_kernel<<<1, 1024>>>(tgt, lossptr);
}

// round 6
// speedup vs baseline: 1.8392x; 1.1203x over previous
#include <cuda_runtime.h>
#include <cuda_fp16.h>
#include <math.h>
#include <stdint.h>

// Problem constants (fixed by the reference)
#define NB 2
#define NT 1024
#define ND 1024
#define NV 32000
#define NL 4
#define NE 2048
#define NN 16
#define NR 64
#define NKC 4
#define NXD 96
#define NBT (NB*NT)

// ---------------- single scratch region (one device symbol) -----------------
constexpr size_t OFF_X     = 0;
constexpr size_t OFF_XZ    = OFF_X     + (size_t)NBT*ND*4;
constexpr size_t OFF_XC    = OFF_XZ    + (size_t)NBT*2*NE*4;
constexpr size_t OFF_DELTA = OFF_XC    + (size_t)NBT*NE*4;
constexpr size_t OFF_XDBL  = OFF_DELTA + (size_t)NBT*NE*4;
constexpr size_t OFF_NLL   = OFF_XDBL  + (size_t)NBT*128*4;
constexpr size_t OFF_XHI   = OFF_NLL   + (size_t)NBT*4;
constexpr size_t OFF_XLO   = OFF_XHI   + (size_t)NBT*ND*2;
constexpr size_t OFF_XCHI  = OFF_XLO   + (size_t)NBT*ND*2;
constexpr size_t OFF_XCLO  = OFF_XCHI  + (size_t)NBT*NE*2;
constexpr size_t OFF_YHI   = OFF_XCLO  + (size_t)NBT*NE*2;
constexpr size_t OFF_YLO   = OFF_YHI   + (size_t)NBT*NE*2;
constexpr size_t OFF_XNHI  = OFF_YLO   + (size_t)NBT*NE*2;
constexpr size_t OFF_XNLO  = OFF_XNHI  + (size_t)NBT*ND*2;
constexpr size_t OFF_XDHI  = OFF_XNLO  + (size_t)NBT*ND*2;
constexpr size_t OFF_XDLO  = OFF_XDHI  + (size_t)NBT*128*2;
constexpr size_t OFF_WI    = OFF_XDLO  + (size_t)NBT*128*2;
constexpr size_t OFF_WO    = OFF_WI    + (size_t)NL*2*NE*ND*2;
constexpr size_t OFF_WP    = OFF_WO    + (size_t)NL*ND*NE*2;
constexpr size_t OFF_WH    = OFF_WP    + (size_t)NL*128*NE*2;
constexpr size_t OFF_WDT   = OFF_WH    + (size_t)NV*ND*2;
constexpr size_t OFF_LOGFB = OFF_WDT   + (size_t)NL*NE*NR*2;
constexpr size_t SCRATCH_SZ = OFF_LOGFB + (size_t)NBT*NV*4;

static __device__ __align__(1024) unsigned char g_scratch[SCRATCH_SZ];

__device__ __forceinline__ float* scr_f(size_t off) {
    return reinterpret_cast<float*>(g_scratch + off);
}
__device__ __forceinline__ __half* scr_h(size_t off) {
    return reinterpret_cast<__half*>(g_scratch + off);
}

// ---------------- helpers ----------------------------------------------------
__device__ __forceinline__ float warpSum(float v) {
#pragma unroll
    for (int o = 16; o > 0; o >>= 1) v += __shfl_xor_sync(0xffffffffu, v, o);
    return v;
}
__device__ __forceinline__ float warpMax(float v) {
#pragma unroll
    for (int o = 16; o > 0; o >>= 1) v = fmaxf(v, __shfl_xor_sync(0xffffffffu, v, o));
    return v;
}
__device__ __forceinline__ float siluf(float x) { return x / (1.0f + __expf(-x)); }

// fp16 two-term split: v ~= hi + lo/2048 with ~2^-22 relative error
__device__ __forceinline__ void split_f16(float v, __half& hi, __half& lo) {
    hi = __float2half_rn(v);
    lo = __float2half_rn((v - __half2float(hi)) * 2048.0f);
}

__device__ __forceinline__ uint32_t smem_u32(const void* p) {
    uint32_t a;
    asm("{ .reg .u64 t; cvta.to.shared.u64 t, %1; cvt.u32.u64 %0, t; }" : "=r"(a) : "l"(p));
    return a;
}
__device__ __forceinline__ uint32_t lds32(uint32_t a) {
    uint32_t v;
    asm volatile("ld.shared.b32 %0, [%1];" : "=r"(v) : "r"(a));
    return v;
}
__device__ __forceinline__ void cpasync16(uint32_t dst, const void* src) {
    asm volatile("cp.async.cg.shared.global [%0], [%1], 16;" :: "r"(dst), "l"(src));
}
__device__ __forceinline__ void cp_commit() {
    asm volatile("cp.async.commit_group;" ::: "memory");
}
template <int N>
__device__ __forceinline__ void cp_wait() {
    asm volatile("cp.async.wait_group %0;" :: "n"(N) : "memory");
}
__device__ __forceinline__ void mma16816(float* c, const uint32_t* a, const uint32_t* b) {
    asm volatile(
        "mma.sync.aligned.m16n8k16.row.col.f32.f16.f16.f32 "
        "{%0,%1,%2,%3},{%4,%5,%6,%7},{%8,%9},{%0,%1,%2,%3};"
        : "+f"(c[0]), "+f"(c[1]), "+f"(c[2]), "+f"(c[3])
        : "r"(a[0]), "r"(a[1]), "r"(a[2]), "r"(a[3]), "r"(b[0]), "r"(b[1]));
}

// ---------------- tensor-core GEMM (fp16 2-term split, mma.sync) -------------
// C[M,N] = A[M,K]*B[N,K]^T.  A given as fp16 (hi, lo*2048) pair; B single fp16.
// 128x128 CTA tile, 256 threads (8 warps 2x4), K-chunks of 32, cp.async double
// buffered.  mode 0: store; 1: C += acc (residual); 2: softplus(acc+bias[col]).
// auxhi/auxlo non-null: also store fp16 split of the final value.
#define TROW 40                 // smem row stride in halves (80B, conflict-free)
#define TILEB (128*TROW*2)      // 10240 bytes per tile
#define GSMEM (2*3*TILEB)       // 61440 bytes (2 stages x {Ahi,Alo,B})

__global__ void __launch_bounds__(256, 1)
gemm_mma(const __half* __restrict__ Ahi, const __half* __restrict__ Alo, int lda,
         const __half* __restrict__ Bw, int ldb,
         float* __restrict__ C, int ldc, int K, int Nreal, int mode,
         const float* __restrict__ bias,
         __half* __restrict__ auxhi, __half* __restrict__ auxlo)
{
    extern __shared__ char dynsmem[];
    const uint32_t sb = smem_u32(dynsmem);
    const int tid = threadIdx.x;
    const int wid = tid >> 5;
    const int lane = tid & 31;
    const int wm = wid >> 2;          // 0..1  (64-row slab)
    const int wn = wid & 3;           // 0..3  (32-col slab)
    const int g = lane >> 2;          // 0..7
    const int t2 = (lane & 3) * 2;

    const int m0 = blockIdx.y * 128;
    const int n0 = blockIdx.x * 128;

    const __half* srcs[3];
    int ldas[3];
    srcs[0] = Ahi + (size_t)m0 * lda;  ldas[0] = lda;
    srcs[1] = Alo + (size_t)m0 * lda;  ldas[1] = lda;
    srcs[2] = Bw  + (size_t)n0 * ldb;  ldas[2] = ldb;

    float acch[4][4][4];
    float accl[4][4][4];
#pragma unroll
    for (int mi = 0; mi < 4; mi++)
#pragma unroll
        for (int ni = 0; ni < 4; ni++)
#pragma unroll
            for (int q = 0; q < 4; q++) { acch[mi][ni][q] = 0.0f; accl[mi][ni][q] = 0.0f; }

    const int nchunks = K >> 5;

    // issue chunk 0 into buf 0
    {
        const uint32_t tb0 = sb;
#pragma unroll
        for (int t = 0; t < 3; t++) {
            const __half* s = srcs[t];
            const int ld = ldas[t];
#pragma unroll
            for (int u = 0; u < 2; u++) {
                const int idx = tid + u * 256;       // 0..511
                const int row = idx >> 2;
                const int seg = idx & 3;
                cpasync16(tb0 + (uint32_t)t * TILEB + (uint32_t)(row * 80 + seg * 16),
                          s + (size_t)row * ld + seg * 8);
            }
        }
        cp_commit();
    }

    for (int c = 0; c < nchunks; c++) {
        const int buf = c & 1;
        if (c + 1 < nchunks) {
            const uint32_t tb1 = sb + (uint32_t)(buf ^ 1) * (3 * TILEB);
            const int k1 = (c + 1) << 5;
#pragma unroll
            for (int t = 0; t < 3; t++) {
                const __half* s = srcs[t] + k1;
                const int ld = ldas[t];
#pragma unroll
                for (int u = 0; u < 2; u++) {
                    const int idx = tid + u * 256;
                    const int row = idx >> 2;
                    const int seg = idx & 3;
                    cpasync16(tb1 + (uint32_t)t * TILEB + (uint32_t)(row * 80 + seg * 16),
                              s + (size_t)row * ld + seg * 8);
                }
            }
            cp_commit();
            cp_wait<1>();
        } else {
            cp_wait<0>();
        }
        __syncthreads();

        const uint32_t aAh = sb + (uint32_t)buf * (3 * TILEB);
        const uint32_t aAl = aAh + TILEB;
        const uint32_t aB  = aAh + 2 * TILEB;

#pragma unroll
        for (int ks = 0; ks < 32; ks += 16) {
            uint32_t ah[4][4], al[4][4];
#pragma unroll
            for (int mi = 0; mi < 4; mi++) {
                const int r0 = wm * 64 + mi * 16 + g;
                const uint32_t o00 = (uint32_t)(r0 * 80 + (ks + t2) * 2);
                const uint32_t o10 = o00 + 8 * 80;
                ah[mi][0] = lds32(aAh + o00);
                ah[mi][1] = lds32(aAh + o10);
                ah[mi][2] = lds32(aAh + o00 + 16);
                ah[mi][3] = lds32(aAh + o10 + 16);
                al[mi][0] = lds32(aAl + o00);
                al[mi][1] = lds32(aAl + o10);
                al[mi][2] = lds32(aAl + o00 + 16);
                al[mi][3] = lds32(aAl + o10 + 16);
            }
            uint32_t bb[4][2];
#pragma unroll
            for (int ni = 0; ni < 4; ni++) {
                const int rb = wn * 32 + ni * 8 + g;
                const uint32_t ob = (uint32_t)(rb * 80 + (ks + t2) * 2);
                bb[ni][0] = lds32(aB + ob);
                bb[ni][1] = lds32(aB + ob + 16);
            }
#pragma unroll
            for (int mi = 0; mi < 4; mi++) {
#pragma unroll
                for (int ni = 0; ni < 4; ni++) {
                    mma16816(acch[mi][ni], ah[mi], bb[ni]);
                    mma16816(accl[mi][ni], al[mi], bb[ni]);
                }
            }
        }
        __syncthreads();
    }

    // epilogue: v = acc_hi + acc_lo / 2048
    const float INVS = 1.0f / 2048.0f;
#pragma unroll
    for (int mi = 0; mi < 4; mi++) {
        const int row0 = m0 + wm * 64 + mi * 16 + g;
        const int row1 = row0 + 8;
#pragma unroll
        for (int ni = 0; ni < 4; ni++) {
            const int col = n0 + wn * 32 + ni * 8 + t2;
            if (col < Nreal) {
                float v0 = acch[mi][ni][0] + accl[mi][ni][0] * INVS;
                float v1 = acch[mi][ni][1] + accl[mi][ni][1] * INVS;
                float v2 = acch[mi][ni][2] + accl[mi][ni][2] * INVS;
                float v3 = acch[mi][ni][3] + accl[mi][ni][3] * INVS;
                float* p0 = C + (size_t)row0 * ldc + col;
                float* p1 = C + (size_t)row1 * ldc + col;
                if (mode == 1) {
                    v0 += p0[0]; v1 += p0[1];
                    v2 += p1[0]; v3 += p1[1];
                } else if (mode == 2) {
                    float b0 = bias[col], b1 = bias[col + 1];
                    v0 += b0; v1 += b1; v2 += b0; v3 += b1;
                    v0 = (v0 > 20.0f) ? v0 : log1pf(__expf(v0));
                    v1 = (v1 > 20.0f) ? v1 : log1pf(__expf(v1));
                    v2 = (v2 > 20.0f) ? v2 : log1pf(__expf(v2));
                    v3 = (v3 > 20.0f) ? v3 : log1pf(__expf(v3));
                }
                p0[0] = v0; p0[1] = v1;
                p1[0] = v2; p1[1] = v3;
                if (auxhi != nullptr) {
                    __half h, l;
                    split_f16(v0, h, l);
                    auxhi[(size_t)row0 * ldc + col] = h;
                    auxlo[(size_t)row0 * ldc + col] = l;
                    split_f16(v1, h, l);
                    auxhi[(size_t)row0 * ldc + col + 1] = h;
                    auxlo[(size_t)row0 * ldc + col + 1] = l;
                    split_f16(v2, h, l);
                    auxhi[(size_t)row1 * ldc + col] = h;
                    auxlo[(size_t)row1 * ldc + col] = l;
                    split_f16(v3, h, l);
                    auxhi[(size_t)row1 * ldc + col + 1] = h;
                    auxlo[(size_t)row1 * ldc + col + 1] = l;
                }
            }
        }
    }
}

// ---------------- weight conversions (single fp16 round) ---------------------
__global__ void cvt_kernel(const float* __restrict__ src,
                           __half* __restrict__ dst, long long n)
{
    long long i = (long long)blockIdx.x * blockDim.x + threadIdx.x;
    if (i >= n) return;
    dst[i] = __float2half_rn(src[i]);
}

// x_proj [L][96][E] -> padded [L][128][E] fp16 (pad rows = 0, written each launch)
__global__ void cvt_xp_kernel(const float* __restrict__ src)
{
    int i = blockIdx.x * blockDim.x + threadIdx.x;
    if (i >= NL * 128 * NE) return;
    int col = i % NE;
    int r = (i / NE) & 127;
    int l = i / (NE * 128);
    float v = 0.0f;
    if (r < NXD) v = src[((size_t)l * NXD + r) * NE + col];
    scr_h(OFF_WP)[i] = __float2half_rn(v);
}

// ---------------- embedding ---------------------------------------------------
__global__ void embed_kernel(const int* __restrict__ ids,
                             const float* __restrict__ tok,
                             const float* __restrict__ pos)
{
    int idx = blockIdx.x * blockDim.x + threadIdx.x;
    if (idx >= NBT * ND) return;
    int d = idx % ND;
    int bt = idx / ND;
    int t = bt % NT;
    float v = tok[(size_t)ids[bt] * ND + d] + pos[(size_t)t * ND + d];
    scr_f(OFF_X)[idx] = v;
    __half h, l;
    split_f16(v, h, l);
    scr_h(OFF_XHI)[idx] = h;
    scr_h(OFF_XLO)[idx] = l;
}

// ---------------- causal depthwise conv + bias + SiLU ------------------------
__global__ void conv_silu_kernel(const float* __restrict__ cw,
                                 const float* __restrict__ cb)
{
    int idx = blockIdx.x * blockDim.x + threadIdx.x;
    if (idx >= NBT * NE) return;
    const float* xz = scr_f(OFF_XZ);
    int e = idx % NE;
    int bt = idx / NE;
    int t = bt % NT;
    float s = cb[e];
#pragma unroll
    for (int k = 0; k < NKC; k++) {
        int tt = t - (NKC - 1) + k;
        if (tt >= 0)
            s += cw[e * NKC + k] * xz[(size_t)(bt - (NKC - 1) + k) * (2 * NE) + e];
    }
    float v = siluf(s);
    scr_f(OFF_XC)[idx] = v;
    __half h, l;
    split_f16(v, h, l);
    scr_h(OFF_XCHI)[idx] = h;
    scr_h(OFF_XCLO)[idx] = l;
}

// ---------------- selective scan + D skip + SiLU(z) gate ---------------------
__global__ void __launch_bounds__(256)
scan_kernel(const float* __restrict__ A_log, const float* __restrict__ Dp)
{
    const int tid = threadIdx.x;
    const int lane = tid & 15;
    const int ch = blockIdx.x * 16 + (tid >> 4);
    const int b = ch >> 11;
    const int e = ch & (NE - 1);

    const float* delta = scr_f(OFF_DELTA);
    const float* xc = scr_f(OFF_XC);
    const float* xdbl = scr_f(OFF_XDBL);
    const float* xz = scr_f(OFF_XZ);
    __half* yhi = scr_h(OFF_YHI);
    __half* ylo = scr_h(OFF_YLO);

    const float Av = -__expf(A_log[e * NN + lane]);
    const float dpar = Dp[e];
    float h = 0.0f;
    const size_t base = (size_t)b * NT;

    for (int t = 0; t < NT; t++) {
        const size_t row = base + t;
        const float dv = delta[row * NE + e];
        const float xv = xc[row * NE + e];
        const float Bv = xdbl[row * 128 + NR + lane];
        const float Cv = xdbl[row * 128 + NR + NN + lane];
        h = __expf(dv * Av) * h + (dv * Bv) * xv;
        float p = h * Cv;
        p += __shfl_xor_sync(0xffffffffu, p, 8);
        p += __shfl_xor_sync(0xffffffffu, p, 4);
        p += __shfl_xor_sync(0xffffffffu, p, 2);
        p += __shfl_xor_sync(0xffffffffu, p, 1);
        if (lane == 0) {
            const float z = xz[row * (2 * NE) + NE + e];
            float v = (p + dpar * xv) * siluf(z);
            __half hh, ll;
            split_f16(v, hh, ll);
            yhi[row * NE + e] = hh;
            ylo[row * NE + e] = ll;
        }
    }
}

// ---------------- LayerNorm ---------------------------------------------------
__global__ void ln_kernel(const float* __restrict__ gam,
                          const float* __restrict__ bet)
{
    __shared__ float sm[8];
    __shared__ float sm2[8];
    const int bt = blockIdx.x;
    const float* row = scr_f(OFF_X) + (size_t)bt * ND;
    float s = 0.f, s2 = 0.f;
    for (int d = threadIdx.x; d < ND; d += 256) {
        float v = row[d];
        s += v;
        s2 += v * v;
    }
    s = warpSum(s);
    s2 = warpSum(s2);
    if ((threadIdx.x & 31) == 0) { sm[threadIdx.x >> 5] = s; sm2[threadIdx.x >> 5] = s2; }
    __syncthreads();
    if (threadIdx.x < 32) {
        float a = (threadIdx.x < 8) ? sm[threadIdx.x] : 0.f;
        float b2 = (threadIdx.x < 8) ? sm2[threadIdx.x] : 0.f;
        a = warpSum(a);
        b2 = warpSum(b2);
        if (threadIdx.x == 0) { sm[0] = a; sm2[0] = b2; }
    }
    __syncthreads();
    const float mu = sm[0] * (1.0f / ND);
    const float var = sm2[0] * (1.0f / ND) - mu * mu;
    const float inv = rsqrtf(var + 1e-5f);
    for (int d = threadIdx.x; d < ND; d += 256) {
        float v = (row[d] - mu) * inv * gam[d] + bet[d];
        __half h, l;
        split_f16(v, h, l);
        scr_h(OFF_XNHI)[(size_t)bt * ND + d] = h;
        scr_h(OFF_XNLO)[(size_t)bt * ND + d] = l;
    }
}

// ---------------- per-token NLL ----------------------------------------------
__global__ void loss_token_kernel(const float* __restrict__ logits,
                                  const int* __restrict__ tgt)
{
    __shared__ float sred[8];
    const int bt = blockIdx.x;
    const float* row = logits + (size_t)bt * NV;

    float m = -1e30f;
    for (int v = threadIdx.x; v < NV; v += 256) m = fmaxf(m, row[v]);
    m = warpMax(m);
    if ((threadIdx.x & 31) == 0) sred[threadIdx.x >> 5] = m;
    __syncthreads();
    if (threadIdx.x < 32) {
        float a = (threadIdx.x < 8) ? sred[threadIdx.x] : -1e30f;
        a = warpMax(a);
        if (threadIdx.x == 0) sred[0] = a;
    }
    __syncthreads();
    m = sred[0];
    __syncthreads();

    float se = 0.f;
    for (int v = threadIdx.x; v < NV; v += 256) se += __expf(row[v] - m);
    se = warpSum(se);
    if ((threadIdx.x & 31) == 0) sred[threadIdx.x >> 5] = se;
    __syncthreads();
    if (threadIdx.x < 32) {
        float a = (threadIdx.x < 8) ? sred[threadIdx.x] : 0.f;
        a = warpSum(a);
        if (threadIdx.x == 0) {
            int tv = tgt[bt];
            float val = 0.0f;
            if (tv != -100) val = -(row[tv] - m - logf(a));
            scr_f(OFF_NLL)[bt] = val;
        }
    }
}

__global__ void loss_reduce_kernel(const int* __restrict__ tgt,
                                   float* __restrict__ outp)
{
    __shared__ float sm[32];
    __shared__ float sc[32];
    float s = 0.f, c = 0.f;
    for (int i = threadIdx.x; i < NBT; i += 1024) {
        s += scr_f(OFF_NLL)[i];
        c += (tgt[i] != -100) ? 1.0f : 0.0f;
    }
    s = warpSum(s);
    c = warpSum(c);
    if ((threadIdx.x & 31) == 0) { sm[threadIdx.x >> 5] = s; sc[threadIdx.x >> 5] = c; }
    __syncthreads();
    if (threadIdx.x < 32) {
        float a = sm[threadIdx.x];
        float b = sc[threadIdx.x];
        a = warpSum(a);
        b = warpSum(b);
        if (threadIdx.x == 0) outp[0] = a / fmaxf(b, 1.0f);
    }
}

// ---------------- host orchestration -----------------------------------------
extern "C" void kernel_launch(void* const* d_in, const int* in_sizes, int n_in,
                              void* d_out, int out_size)
{
    const int* ids = (const int*)d_in[0];
    const int* tgt = (const int*)d_in[1];
    const float* tok_emb = (const float*)d_in[2];
    const float* pos_emb = (const float*)d_in[3];
    const float* ln_g = (const float*)d_in[4];
    const float* ln_b = (const float*)d_in[5];
    const float* head_w = (const float*)d_in[6];
    const float* in_proj_w = (const float*)d_in[7];
    const float* conv_w = (const float*)d_in[8];
    const float* conv_b = (const float*)d_in[9];
    const float* x_proj_w = (const float*)d_in[10];
    const float* dt_proj_w = (const float*)d_in[11];
    const float* dt_proj_b = (const float*)d_in[12];
    const float* A_log = (const float*)d_in[13];
    const float* D_param = (const float*)d_in[14];
    const float* out_proj_w = (const float*)d_in[15];
    float* out = (float*)d_out;

    unsigned char* base = 0;
    cudaGetSymbolAddress((void**)&base, g_scratch);

    float* p_x = (float*)(base + OFF_X);
    float* p_xz = (float*)(base + OFF_XZ);
    float* p_xdbl = (float*)(base + OFF_XDBL);
    float* p_delta = (float*)(base + OFF_DELTA);
    float* p_logfb = (float*)(base + OFF_LOGFB);
    __half* p_xhi = (__half*)(base + OFF_XHI);
    __half* p_xlo = (__half*)(base + OFF_XLO);
    __half* p_xchi = (__half*)(base + OFF_XCHI);
    __half* p_xclo = (__half*)(base + OFF_XCLO);
    __half* p_yhi = (__half*)(base + OFF_YHI);
    __half* p_ylo = (__half*)(base + OFF_YLO);
    __half* p_xnhi = (__half*)(base + OFF_XNHI);
    __half* p_xnlo = (__half*)(base + OFF_XNLO);
    __half* p_xdhi = (__half*)(base + OFF_XDHI);
    __half* p_xdlo = (__half*)(base + OFF_XDLO);
    __half* p_wi = (__half*)(base + OFF_WI);
    __half* p_wo = (__half*)(base + OFF_WO);
    __half* p_wp = (__half*)(base + OFF_WP);
    __half* p_wh = (__half*)(base + OFF_WH);
    __half* p_wdt = (__half*)(base + OFF_WDT);

    cudaFuncSetAttribute(gemm_mma, cudaFuncAttributeMaxDynamicSharedMemorySize, GSMEM);

    const long long NLOGITS = (long long)NBT * NV;

    // 0) weight conversions (rebuilt every launch; deterministic)
    {
        long long n1 = (long long)NL * 2 * NE * ND;
        cvt_kernel<<<(int)((n1 + 255) / 256), 256>>>(in_proj_w, p_wi, n1);
        long long n2 = (long long)NL * ND * NE;
        cvt_kernel<<<(int)((n2 + 255) / 256), 256>>>(out_proj_w, p_wo, n2);
        long long n3 = (long long)NV * ND;
        cvt_kernel<<<(int)((n3 + 255) / 256), 256>>>(head_w, p_wh, n3);
        long long n4 = (long long)NL * NE * NR;
        cvt_kernel<<<(int)((n4 + 255) / 256), 256>>>(dt_proj_w, p_wdt, n4);
        cvt_xp_kernel<<<(NL * 128 * NE + 255) / 256, 256>>>(x_proj_w);
    }

    // 1) embedding
    embed_kernel<<<(NBT * ND + 255) / 256, 256>>>(ids, tok_emb, pos_emb);

    // 2) layers
    for (int l = 0; l < NL; l++) {
        // xz = x @ in_proj^T   [2048 x 4096], K=1024
        gemm_mma<<<dim3(32, 16), 256, GSMEM>>>(
            p_xhi, p_xlo, ND,
            p_wi + (size_t)l * 2 * NE * ND, ND,
            p_xz, 2 * NE, ND, 2 * NE, 0, nullptr, nullptr, nullptr);

        // conv + SiLU -> xc
        conv_silu_kernel<<<(NBT * NE + 255) / 256, 256>>>(
            conv_w + (size_t)l * NE * NKC, conv_b + (size_t)l * NE);

        // x_dbl = xc @ x_proj^T   [2048 x 96] (N padded to 128), K=2048
        // fp32 out for scan + fp16 split aux for the dt GEMM
        gemm_mma<<<dim3(1, 16), 256, GSMEM>>>(
            p_xchi, p_xclo, NE,
            p_wp + (size_t)l * 128 * NE, NE,
            p_xdbl, 128, NE, 128, 0, nullptr, p_xdhi, p_xdlo);

        // delta = softplus(x_dbl[:, :64] @ dt_proj^T + b)  [2048 x 2048], K=64
        gemm_mma<<<dim3(16, 16), 256, GSMEM>>>(
            p_xdhi, p_xdlo, 128,
            p_wdt + (size_t)l * NE * NR, NR,
            p_delta, NE, NR, NE, 2, dt_proj_b + (size_t)l * NE, nullptr, nullptr);

        // selective scan -> y (fp16 split)
        scan_kernel<<<(NB * NE) / 16, 256>>>(
            A_log + (size_t)l * NE * NN, D_param + (size_t)l * NE);

        // x += y @ out_proj^T   [2048 x 1024], K=2048; fused x split refresh
        gemm_mma<<<dim3(8, 16), 256, GSMEM>>>(
            p_yhi, p_ylo, NE,
            p_wo + (size_t)l * ND * NE, NE,
            p_x, ND, NE, ND, 1, nullptr, p_xhi, p_xlo);
    }

    // 3) final LayerNorm
    ln_kernel<<<NBT, 256>>>(ln_g, ln_b);

    // 4) head GEMM -> logits  [2048 x 32000], K=1024
    float* logits = ((long long)out_size >= NLOGITS) ? out : p_logfb;
    gemm_mma<<<dim3(250, 16), 256, GSMEM>>>(
        p_xnhi, p_xnlo, ND, p_wh, ND,
        logits, NV, ND, NV, 0, nullptr, nullptr, nullptr);

    // 5) loss
    loss_token_kernel<<<NBT, 256>>>(logits, tgt);
    float* lossptr = nullptr;
    if ((long long)out_size > NLOGITS) lossptr = out + NLOGITS;
    else if ((long long)out_size < NLOGITS) lossptr = out;
    if (lossptr != nullptr)
        loss_reduce_kernel<<<1, 1024>>>(tgt, lossptr);
}

// round 7
// speedup vs baseline: 2.4079x; 1.3093x over previous
#include <cuda_runtime.h>
#include <cuda_fp16.h>
#include <math.h>
#include <stdint.h>

// Problem constants (fixed by the reference)
#define NB 2
#define NT 1024
#define ND 1024
#define NV 32000
#define NL 4
#define NE 2048
#define NN 16
#define NR 64
#define NKC 4
#define NXD 96
#define NBT (NB*NT)
#define KSPL 8

// ---------------- single scratch region (one device symbol) -----------------
constexpr size_t OFF_X     = 0;
constexpr size_t OFF_XZ    = OFF_X     + (size_t)NBT*ND*4;
constexpr size_t OFF_XC    = OFF_XZ    + (size_t)NBT*2*NE*4;
constexpr size_t OFF_DELTA = OFF_XC    + (size_t)NBT*NE*4;
constexpr size_t OFF_XDBL  = OFF_DELTA + (size_t)NBT*NE*4;
constexpr size_t OFF_XSPK  = OFF_XDBL  + (size_t)NBT*128*4;
constexpr size_t OFF_NLL   = OFF_XSPK  + (size_t)KSPL*NBT*128*4;
constexpr size_t OFF_XH    = OFF_NLL   + (size_t)NBT*4;
constexpr size_t OFF_XCH   = OFF_XH    + (size_t)NBT*ND*2;
constexpr size_t OFF_YH    = OFF_XCH   + (size_t)NBT*NE*2;
constexpr size_t OFF_XNH   = OFF_YH    + (size_t)NBT*NE*2;
constexpr size_t OFF_XDH   = OFF_XNH   + (size_t)NBT*ND*2;
constexpr size_t OFF_WI    = OFF_XDH   + (size_t)NBT*128*2;
constexpr size_t OFF_WO    = OFF_WI    + (size_t)NL*2*NE*ND*2;
constexpr size_t OFF_WP    = OFF_WO    + (size_t)NL*ND*NE*2;
constexpr size_t OFF_WH    = OFF_WP    + (size_t)NL*128*NE*2;
constexpr size_t OFF_WDT   = OFF_WH    + (size_t)NV*ND*2;
constexpr size_t OFF_LOGFB = OFF_WDT   + (size_t)NL*NE*NR*2;
constexpr size_t SCRATCH_SZ = OFF_LOGFB + (size_t)NBT*NV*4;

static __device__ __align__(1024) unsigned char g_scratch[SCRATCH_SZ];

__device__ __forceinline__ float* scr_f(size_t off) {
    return reinterpret_cast<float*>(g_scratch + off);
}
__device__ __forceinline__ __half* scr_h(size_t off) {
    return reinterpret_cast<__half*>(g_scratch + off);
}

// ---------------- helpers ----------------------------------------------------
__device__ __forceinline__ float warpSum(float v) {
#pragma unroll
    for (int o = 16; o > 0; o >>= 1) v += __shfl_xor_sync(0xffffffffu, v, o);
    return v;
}
__device__ __forceinline__ float warpMax(float v) {
#pragma unroll
    for (int o = 16; o > 0; o >>= 1) v = fmaxf(v, __shfl_xor_sync(0xffffffffu, v, o));
    return v;
}
__device__ __forceinline__ float siluf(float x) { return x / (1.0f + __expf(-x)); }

__device__ __forceinline__ uint32_t smem_u32(const void* p) {
    uint32_t a;
    asm("{ .reg .u64 t; cvta.to.shared.u64 t, %1; cvt.u32.u64 %0, t; }" : "=r"(a) : "l"(p));
    return a;
}
__device__ __forceinline__ void cpasync16(uint32_t dst, const void* src) {
    asm volatile("cp.async.cg.shared.global [%0], [%1], 16;" :: "r"(dst), "l"(src));
}
__device__ __forceinline__ void cp_commit() {
    asm volatile("cp.async.commit_group;" ::: "memory");
}
template <int N>
__device__ __forceinline__ void cp_wait() {
    asm volatile("cp.async.wait_group %0;" :: "n"(N) : "memory");
}
__device__ __forceinline__ void ldsm4(uint32_t* r, uint32_t addr) {
    asm volatile("ldmatrix.sync.aligned.m8n8.x4.shared.b16 {%0,%1,%2,%3}, [%4];"
                 : "=r"(r[0]), "=r"(r[1]), "=r"(r[2]), "=r"(r[3]) : "r"(addr));
}
__device__ __forceinline__ void mma16816(float* c, const uint32_t* a, const uint32_t* b) {
    asm volatile(
        "mma.sync.aligned.m16n8k16.row.col.f32.f16.f16.f32 "
        "{%0,%1,%2,%3},{%4,%5,%6,%7},{%8,%9},{%0,%1,%2,%3};"
        : "+f"(c[0]), "+f"(c[1]), "+f"(c[2]), "+f"(c[3])
        : "r"(a[0]), "r"(a[1]), "r"(a[2]), "r"(a[3]), "r"(b[0]), "r"(b[1]));
}

// ---------------- tensor-core GEMM (fp16, mma.sync + ldmatrix) ---------------
// C[M,N] = A[M,K]*B[N,K]^T. Both operands fp16, row-major, K%32==0.
// 128x128 CTA tile, 256 threads (8 warps 2x4), K-chunks of 32, cp.async double
// buffered, 2 CTAs/SM. gridDim.z>1 = split-K: slice z handles K columns
// [z*K..(z+1)*K), writes C + z*cSliceStride.
// mode 0: store; 1: C += acc; 2: softplus(acc+bias[col]).
// auxh non-null: also store fp16 of final value.
#define TROW 40                 // smem row stride in halves (80B, conflict-free)
#define TILEB (128*TROW*2)      // 10240 bytes per tile
#define GSMEM (2*2*TILEB)       // 40960 bytes (2 stages x {A,B})

__global__ void __launch_bounds__(256, 2)
gemm_mma(const __half* __restrict__ A, int lda,
         const __half* __restrict__ Bw, int ldb,
         float* __restrict__ C, int ldc, int K, int Nreal, int mode,
         const float* __restrict__ bias, __half* __restrict__ auxh,
         size_t cSliceStride)
{
    extern __shared__ char dynsmem[];
    const uint32_t sb = smem_u32(dynsmem);
    const int tid = threadIdx.x;
    const int wid = tid >> 5;
    const int lane = tid & 31;
    const int wm = wid >> 2;          // 0..1  (64-row slab)
    const int wn = wid & 3;           // 0..3  (32-col slab)
    const int g = lane >> 2;          // 0..7
    const int t2 = (lane & 3) * 2;

    const int m0 = blockIdx.y * 128;
    const int n0 = blockIdx.x * 128;
    const int kz = blockIdx.z;

    const __half* Asrc = A + (size_t)m0 * lda + (size_t)kz * K;
    const __half* Bsrc = Bw + (size_t)n0 * ldb + (size_t)kz * K;
    C += (size_t)kz * cSliceStride;

    float acc[4][4][4];
#pragma unroll
    for (int mi = 0; mi < 4; mi++)
#pragma unroll
        for (int ni = 0; ni < 4; ni++)
#pragma unroll
            for (int q = 0; q < 4; q++) acc[mi][ni][q] = 0.0f;

    const int nchunks = K >> 5;

    // cp.async loader mapping: flat id = t*512 + row*4 + seg
    const int l_row = (tid >> 1) & 127;        // for ids tid, tid+256: t=0 rows
    // We'll just recompute per transfer below for clarity.

    // issue chunk 0 into buf 0
    {
        const uint32_t tb0 = sb;
#pragma unroll
        for (int u = 0; u < 4; u++) {
            const int idx = tid + u * 256;       // 0..1023
            const int t = idx >> 9;              // 0..1
            const int row = (idx >> 2) & 127;
            const int seg = idx & 3;
            const __half* s = (t == 0) ? (Asrc + (size_t)row * lda + seg * 8)
                                       : (Bsrc + (size_t)row * ldb + seg * 8);
            cpasync16(tb0 + (uint32_t)t * TILEB + (uint32_t)(row * 80 + seg * 16), s);
        }
        cp_commit();
    }

    // per-lane ldmatrix row/col offsets
    const uint32_t aRow = (uint32_t)(wm * 64 + (lane & 15));
    const uint32_t aKoff = (uint32_t)(((lane >> 4) & 1) * 16);
    const uint32_t bRow = (uint32_t)(wn * 32 + (lane & 7) + ((lane & 16) ? 8 : 0));
    const uint32_t bKoff = (uint32_t)(((lane >> 3) & 1) * 16);

    for (int c = 0; c < nchunks; c++) {
        const int buf = c & 1;
        if (c + 1 < nchunks) {
            const uint32_t tb1 = sb + (uint32_t)(buf ^ 1) * (2 * TILEB);
            const int k1 = (c + 1) << 5;
#pragma unroll
            for (int u = 0; u < 4; u++) {
                const int idx = tid + u * 256;
                const int t = idx >> 9;
                const int row = (idx >> 2) & 127;
                const int seg = idx & 3;
                const __half* s = (t == 0) ? (Asrc + (size_t)row * lda + k1 + seg * 8)
                                           : (Bsrc + (size_t)row * ldb + k1 + seg * 8);
                cpasync16(tb1 + (uint32_t)t * TILEB + (uint32_t)(row * 80 + seg * 16), s);
            }
            cp_commit();
            cp_wait<1>();
        } else {
            cp_wait<0>();
        }
        __syncthreads();

        const uint32_t baseA = sb + (uint32_t)buf * (2 * TILEB);
        const uint32_t baseB = baseA + TILEB;

#pragma unroll
        for (int ks = 0; ks < 2; ks++) {
            const uint32_t ksB = (uint32_t)(ks * 32);   // 16 halves = 32 bytes
            uint32_t ah[4][4];
#pragma unroll
            for (int mi = 0; mi < 4; mi++)
                ldsm4(ah[mi], baseA + (aRow + mi * 16) * 80 + aKoff + ksB);
            uint32_t b01[4], b23[4];
            ldsm4(b01, baseB + bRow * 80 + bKoff + ksB);
            ldsm4(b23, baseB + (bRow + 16) * 80 + bKoff + ksB);
#pragma unroll
            for (int mi = 0; mi < 4; mi++) {
                mma16816(acc[mi][0], ah[mi], b01);
                mma16816(acc[mi][1], ah[mi], b01 + 2);
                mma16816(acc[mi][2], ah[mi], b23);
                mma16816(acc[mi][3], ah[mi], b23 + 2);
            }
        }
        __syncthreads();
    }

    // epilogue
#pragma unroll
    for (int mi = 0; mi < 4; mi++) {
        const int row0 = m0 + wm * 64 + mi * 16 + g;
        const int row1 = row0 + 8;
#pragma unroll
        for (int ni = 0; ni < 4; ni++) {
            const int col = n0 + wn * 32 + ni * 8 + t2;
            if (col < Nreal) {
                float v0 = acc[mi][ni][0];
                float v1 = acc[mi][ni][1];
                float v2 = acc[mi][ni][2];
                float v3 = acc[mi][ni][3];
                float* p0 = C + (size_t)row0 * ldc + col;
                float* p1 = C + (size_t)row1 * ldc + col;
                if (mode == 1) {
                    v0 += p0[0]; v1 += p0[1];
                    v2 += p1[0]; v3 += p1[1];
                } else if (mode == 2) {
                    float b0 = bias[col], b1 = bias[col + 1];
                    v0 += b0; v1 += b1; v2 += b0; v3 += b1;
                    v0 = (v0 > 20.0f) ? v0 : log1pf(__expf(v0));
                    v1 = (v1 > 20.0f) ? v1 : log1pf(__expf(v1));
                    v2 = (v2 > 20.0f) ? v2 : log1pf(__expf(v2));
                    v3 = (v3 > 20.0f) ? v3 : log1pf(__expf(v3));
                }
                p0[0] = v0; p0[1] = v1;
                p1[0] = v2; p1[1] = v3;
                if (auxh != nullptr) {
                    auxh[(size_t)row0 * ldc + col]     = __float2half_rn(v0);
                    auxh[(size_t)row0 * ldc + col + 1] = __float2half_rn(v1);
                    auxh[(size_t)row1 * ldc + col]     = __float2half_rn(v2);
                    auxh[(size_t)row1 * ldc + col + 1] = __float2half_rn(v3);
                }
            }
        }
    }
}

// ---------------- split-K reduction for x_proj -------------------------------
__global__ void spk_reduce_kernel()
{
    int i = blockIdx.x * blockDim.x + threadIdx.x;
    if (i >= NBT * 128) return;
    const float* part = scr_f(OFF_XSPK);
    float s = 0.0f;
#pragma unroll
    for (int z = 0; z < KSPL; z++) s += part[(size_t)z * NBT * 128 + i];
    scr_f(OFF_XDBL)[i] = s;
    scr_h(OFF_XDH)[i] = __float2half_rn(s);
}

// ---------------- weight conversions (vectorized fp16 round) -----------------
__global__ void cvt_kernel(const float* __restrict__ src,
                           __half* __restrict__ dst, long long n4)
{
    long long i = (long long)blockIdx.x * blockDim.x + threadIdx.x;
    if (i >= n4) return;
    float4 v = reinterpret_cast<const float4*>(src)[i];
    __half2 a = __floats2half2_rn(v.x, v.y);
    __half2 b = __floats2half2_rn(v.z, v.w);
    reinterpret_cast<__half2*>(dst)[i * 2] = a;
    reinterpret_cast<__half2*>(dst)[i * 2 + 1] = b;
}

// x_proj [L][96][E] -> padded [L][128][E] fp16 (pad rows = 0, written each launch)
__global__ void cvt_xp_kernel(const float* __restrict__ src)
{
    int i = blockIdx.x * blockDim.x + threadIdx.x;
    if (i >= NL * 128 * NE) return;
    int col = i % NE;
    int r = (i / NE) & 127;
    int l = i / (NE * 128);
    float v = 0.0f;
    if (r < NXD) v = src[((size_t)l * NXD + r) * NE + col];
    scr_h(OFF_WP)[i] = __float2half_rn(v);
}

// ---------------- embedding ---------------------------------------------------
__global__ void embed_kernel(const int* __restrict__ ids,
                             const float* __restrict__ tok,
                             const float* __restrict__ pos)
{
    int idx = blockIdx.x * blockDim.x + threadIdx.x;
    if (idx >= NBT * ND) return;
    int d = idx % ND;
    int bt = idx / ND;
    int t = bt % NT;
    float v = tok[(size_t)ids[bt] * ND + d] + pos[(size_t)t * ND + d];
    scr_f(OFF_X)[idx] = v;
    scr_h(OFF_XH)[idx] = __float2half_rn(v);
}

// ---------------- causal depthwise conv + bias + SiLU ------------------------
__global__ void conv_silu_kernel(const float* __restrict__ cw,
                                 const float* __restrict__ cb)
{
    int idx = blockIdx.x * blockDim.x + threadIdx.x;
    if (idx >= NBT * NE) return;
    const float* xz = scr_f(OFF_XZ);
    int e = idx % NE;
    int bt = idx / NE;
    int t = bt % NT;
    float s = cb[e];
#pragma unroll
    for (int k = 0; k < NKC; k++) {
        int tt = t - (NKC - 1) + k;
        if (tt >= 0)
            s += cw[e * NKC + k] * xz[(size_t)(bt - (NKC - 1) + k) * (2 * NE) + e];
    }
    float v = siluf(s);
    scr_f(OFF_XC)[idx] = v;
    scr_h(OFF_XCH)[idx] = __float2half_rn(v);
}

// ---------------- selective scan + D skip + SiLU(z) gate ---------------------
__global__ void __launch_bounds__(256)
scan_kernel(const float* __restrict__ A_log, const float* __restrict__ Dp)
{
    const int tid = threadIdx.x;
    const int lane = tid & 15;
    const int ch = blockIdx.x * 16 + (tid >> 4);
    const int b = ch >> 11;
    const int e = ch & (NE - 1);

    const float* delta = scr_f(OFF_DELTA);
    const float* xc = scr_f(OFF_XC);
    const float* xdbl = scr_f(OFF_XDBL);
    const float* xz = scr_f(OFF_XZ);
    __half* yh = scr_h(OFF_YH);

    const float Av = -__expf(A_log[e * NN + lane]);
    const float dpar = Dp[e];
    float h = 0.0f;
    const size_t base = (size_t)b * NT;

    for (int t = 0; t < NT; t++) {
        const size_t row = base + t;
        const float dv = delta[row * NE + e];
        const float xv = xc[row * NE + e];
        const float Bv = xdbl[row * 128 + NR + lane];
        const float Cv = xdbl[row * 128 + NR + NN + lane];
        h = __expf(dv * Av) * h + (dv * Bv) * xv;
        float p = h * Cv;
        p += __shfl_xor_sync(0xffffffffu, p, 8);
        p += __shfl_xor_sync(0xffffffffu, p, 4);
        p += __shfl_xor_sync(0xffffffffu, p, 2);
        p += __shfl_xor_sync(0xffffffffu, p, 1);
        if (lane == 0) {
            const float z = xz[row * (2 * NE) + NE + e];
            float v = (p + dpar * xv) * siluf(z);
            yh[row * NE + e] = __float2half_rn(v);
        }
    }
}

// ---------------- LayerNorm ---------------------------------------------------
__global__ void ln_kernel(const float* __restrict__ gam,
                          const float* __restrict__ bet)
{
    __shared__ float sm[8];
    __shared__ float sm2[8];
    const int bt = blockIdx.x;
    const float* row = scr_f(OFF_X) + (size_t)bt * ND;
    float s = 0.f, s2 = 0.f;
    for (int d = threadIdx.x; d < ND; d += 256) {
        float v = row[d];
        s += v;
        s2 += v * v;
    }
    s = warpSum(s);
    s2 = warpSum(s2);
    if ((threadIdx.x & 31) == 0) { sm[threadIdx.x >> 5] = s; sm2[threadIdx.x >> 5] = s2; }
    __syncthreads();
    if (threadIdx.x < 32) {
        float a = (threadIdx.x < 8) ? sm[threadIdx.x] : 0.f;
        float b2 = (threadIdx.x < 8) ? sm2[threadIdx.x] : 0.f;
        a = warpSum(a);
        b2 = warpSum(b2);
        if (threadIdx.x == 0) { sm[0] = a; sm2[0] = b2; }
    }
    __syncthreads();
    const float mu = sm[0] * (1.0f / ND);
    const float var = sm2[0] * (1.0f / ND) - mu * mu;
    const float inv = rsqrtf(var + 1e-5f);
    for (int d = threadIdx.x; d < ND; d += 256) {
        float v = (row[d] - mu) * inv * gam[d] + bet[d];
        scr_h(OFF_XNH)[(size_t)bt * ND + d] = __float2half_rn(v);
    }
}

// ---------------- per-token NLL ----------------------------------------------
__global__ void loss_token_kernel(const float* __restrict__ logits,
                                  const int* __restrict__ tgt)
{
    __shared__ float sred[8];
    const int bt = blockIdx.x;
    const float* row = logits + (size_t)bt * NV;

    float m = -1e30f;
    for (int v = threadIdx.x; v < NV; v += 256) m = fmaxf(m, row[v]);
    m = warpMax(m);
    if ((threadIdx.x & 31) == 0) sred[threadIdx.x >> 5] = m;
    __syncthreads();
    if (threadIdx.x < 32) {
        float a = (threadIdx.x < 8) ? sred[threadIdx.x] : -1e30f;
        a = warpMax(a);
        if (threadIdx.x == 0) sred[0] = a;
    }
    __syncthreads();
    m = sred[0];
    __syncthreads();

    float se = 0.f;
    for (int v = threadIdx.x; v < NV; v += 256) se += __expf(row[v] - m);
    se = warpSum(se);
    if ((threadIdx.x & 31) == 0) sred[threadIdx.x >> 5] = se;
    __syncthreads();
    if (threadIdx.x < 32) {
        float a = (threadIdx.x < 8) ? sred[threadIdx.x] : 0.f;
        a = warpSum(a);
        if (threadIdx.x == 0) {
            int tv = tgt[bt];
            float val = 0.0f;
            if (tv != -100) val = -(row[tv] - m - logf(a));
            scr_f(OFF_NLL)[bt] = val;
        }
    }
}

__global__ void loss_reduce_kernel(const int* __restrict__ tgt,
                                   float* __restrict__ outp)
{
    __shared__ float sm[32];
    __shared__ float sc[32];
    float s = 0.f, c = 0.f;
    for (int i = threadIdx.x; i < NBT; i += 1024) {
        s += scr_f(OFF_NLL)[i];
        c += (tgt[i] != -100) ? 1.0f : 0.0f;
    }
    s = warpSum(s);
    c = warpSum(c);
    if ((threadIdx.x & 31) == 0) { sm[threadIdx.x >> 5] = s; sc[threadIdx.x >> 5] = c; }
    __syncthreads();
    if (threadIdx.x < 32) {
        float a = sm[threadIdx.x];
        float b = sc[threadIdx.x];
        a = warpSum(a);
        b = warpSum(b);
        if (threadIdx.x == 0) outp[0] = a / fmaxf(b, 1.0f);
    }
}

// ---------------- host orchestration -----------------------------------------
extern "C" void kernel_launch(void* const* d_in, const int* in_sizes, int n_in,
                              void* d_out, int out_size)
{
    const int* ids = (const int*)d_in[0];
    const int* tgt = (const int*)d_in[1];
    const float* tok_emb = (const float*)d_in[2];
    const float* pos_emb = (const float*)d_in[3];
    const float* ln_g = (const float*)d_in[4];
    const float* ln_b = (const float*)d_in[5];
    const float* head_w = (const float*)d_in[6];
    const float* in_proj_w = (const float*)d_in[7];
    const float* conv_w = (const float*)d_in[8];
    const float* conv_b = (const float*)d_in[9];
    const float* x_proj_w = (const float*)d_in[10];
    const float* dt_proj_w = (const float*)d_in[11];
    const float* dt_proj_b = (const float*)d_in[12];
    const float* A_log = (const float*)d_in[13];
    const float* D_param = (const float*)d_in[14];
    const float* out_proj_w = (const float*)d_in[15];
    float* out = (float*)d_out;

    unsigned char* base = 0;
    cudaGetSymbolAddress((void**)&base, g_scratch);

    float* p_x = (float*)(base + OFF_X);
    float* p_xz = (float*)(base + OFF_XZ);
    float* p_delta = (float*)(base + OFF_DELTA);
    float* p_xspk = (float*)(base + OFF_XSPK);
    float* p_logfb = (float*)(base + OFF_LOGFB);
    __half* p_xh = (__half*)(base + OFF_XH);
    __half* p_xch = (__half*)(base + OFF_XCH);
    __half* p_yh = (__half*)(base + OFF_YH);
    __half* p_xnh = (__half*)(base + OFF_XNH);
    __half* p_xdh = (__half*)(base + OFF_XDH);
    __half* p_wi = (__half*)(base + OFF_WI);
    __half* p_wo = (__half*)(base + OFF_WO);
    __half* p_wp = (__half*)(base + OFF_WP);
    __half* p_wh = (__half*)(base + OFF_WH);
    __half* p_wdt = (__half*)(base + OFF_WDT);

    cudaFuncSetAttribute(gemm_mma, cudaFuncAttributeMaxDynamicSharedMemorySize, GSMEM);

    const long long NLOGITS = (long long)NBT * NV;

    // 0) weight conversions (rebuilt every launch; deterministic)
    {
        long long n1 = (long long)NL * 2 * NE * ND / 4;
        cvt_kernel<<<(int)((n1 + 255) / 256), 256>>>(in_proj_w, p_wi, n1);
        long long n2 = (long long)NL * ND * NE / 4;
        cvt_kernel<<<(int)((n2 + 255) / 256), 256>>>(out_proj_w, p_wo, n2);
        long long n3 = (long long)NV * ND / 4;
        cvt_kernel<<<(int)((n3 + 255) / 256), 256>>>(head_w, p_wh, n3);
        long long n4 = (long long)NL * NE * NR / 4;
        cvt_kernel<<<(int)((n4 + 255) / 256), 256>>>(dt_proj_w, p_wdt, n4);
        cvt_xp_kernel<<<(NL * 128 * NE + 255) / 256, 256>>>(x_proj_w);
    }

    // 1) embedding
    embed_kernel<<<(NBT * ND + 255) / 256, 256>>>(ids, tok_emb, pos_emb);

    // 2) layers
    for (int l = 0; l < NL; l++) {
        // xz = x @ in_proj^T   [2048 x 4096], K=1024
        gemm_mma<<<dim3(32, 16, 1), 256, GSMEM>>>(
            p_xh, ND, p_wi + (size_t)l * 2 * NE * ND, ND,
            p_xz, 2 * NE, ND, 2 * NE, 0, nullptr, nullptr, 0);

        // conv + SiLU -> xc
        conv_silu_kernel<<<(NBT * NE + 255) / 256, 256>>>(
            conv_w + (size_t)l * NE * NKC, conv_b + (size_t)l * NE);

        // x_dbl partials (split-K x8): [2048 x 128], Kslice=256
        gemm_mma<<<dim3(1, 16, KSPL), 256, GSMEM>>>(
            p_xch, NE, p_wp + (size_t)l * 128 * NE, NE,
            p_xspk, 128, NE / KSPL, 128, 0, nullptr, nullptr,
            (size_t)NBT * 128);
        spk_reduce_kernel<<<(NBT * 128 + 255) / 256, 256>>>();

        // delta = softplus(x_dbl[:, :64] @ dt_proj^T + b)  [2048 x 2048], K=64
        gemm_mma<<<dim3(16, 16, 1), 256, GSMEM>>>(
            p_xdh, 128, p_wdt + (size_t)l * NE * NR, NR,
            p_delta, NE, NR, NE, 2, dt_proj_b + (size_t)l * NE, nullptr, 0);

        // selective scan -> y (fp16)
        scan_kernel<<<(NB * NE) / 16, 256>>>(
            A_log + (size_t)l * NE * NN, D_param + (size_t)l * NE);

        // x += y @ out_proj^T   [2048 x 1024], K=2048; fused x fp16 refresh
        gemm_mma<<<dim3(8, 16, 1), 256, GSMEM>>>(
            p_yh, NE, p_wo + (size_t)l * ND * NE, NE,
            p_x, ND, NE, ND, 1, nullptr, p_xh, 0);
    }

    // 3) final LayerNorm
    ln_kernel<<<NBT, 256>>>(ln_g, ln_b);

    // 4) head GEMM -> logits  [2048 x 32000], K=1024
    float* logits = ((long long)out_size >= NLOGITS) ? out : p_logfb;
    gemm_mma<<<dim3(250, 16, 1), 256, GSMEM>>>(
        p_xnh, ND, p_wh, ND,
        logits, NV, ND, NV, 0, nullptr, nullptr, 0);

    // 5) loss
    loss_token_kernel<<<NBT, 256>>>(logits, tgt);
    float* lossptr = nullptr;
    if ((long long)out_size > NLOGITS) lossptr = out + NLOGITS;
    else if ((long long)out_size < NLOGITS) lossptr = out;
    if (lossptr != nullptr)
        loss_reduce_kernel<<<1, 1024>>>(tgt, lossptr);
}